// round 4
// baseline (speedup 1.0000x reference)
#include <cuda_runtime.h>
#include <math_constants.h>

#define L 1024
#define CS 256
#define CZ 128
#define NH 8
#define DH 32
#define NSPLIT 4
#define BM 64
#define BN 64
#define LN_EPS 1e-5f
#define QK_SCALE 0.17677669529663687f  // 1/sqrt(32)

// ---------------- scratch (device globals; no allocation allowed) ----------------
__device__ float d_sln[L * CS];
__device__ float d_Q[L * CS];
__device__ float d_K[L * CS];
__device__ float d_V[L * CS];
__device__ float d_G[L * CS];
__device__ float d_Bt[(size_t)L * NH * L];             // bias transposed: [i][h][j], 32 MB
__device__ float d_AO[L * CS];                         // G * attn_out
__device__ float d_pO[NSPLIT * NH * L * DH];           // split attention partial O
__device__ float2 d_pml[NSPLIT * NH * L];              // split attention partial (m, l)

// ---------------- Kernel 1: LayerNorm(s) ----------------
__global__ __launch_bounds__(256) void ln_s_kernel(const float* __restrict__ s,
                                                   const float* __restrict__ g,
                                                   const float* __restrict__ b) {
    int r = blockIdx.x, t = threadIdx.x;
    float v = s[r * CS + t];
    __shared__ float red[8];

    float sum = v;
#pragma unroll
    for (int off = 16; off > 0; off >>= 1) sum += __shfl_xor_sync(0xffffffffu, sum, off);
    if ((t & 31) == 0) red[t >> 5] = sum;
    __syncthreads();
    float tot = 0.f;
#pragma unroll
    for (int k = 0; k < 8; k++) tot += red[k];
    float mean = tot * (1.f / CS);
    float d = v - mean;
    __syncthreads();

    float sq = d * d;
#pragma unroll
    for (int off = 16; off > 0; off >>= 1) sq += __shfl_xor_sync(0xffffffffu, sq, off);
    if ((t & 31) == 0) red[t >> 5] = sq;
    __syncthreads();
    float tot2 = 0.f;
#pragma unroll
    for (int k = 0; k < 8; k++) tot2 += red[k];
    float rstd = rsqrtf(tot2 * (1.f / CS) + LN_EPS);

    d_sln[r * CS + t] = d * rstd * g[t] + b[t];
}

// ---------------- shared GEMM tile helper: C[64x64] tile of (A[1024x256] @ B[256x256]) ----------------
__device__ __forceinline__ void gemm_tile_64x64(const float* __restrict__ A,
                                                const float* __restrict__ Bm,
                                                int m0, int n0, float acc[4][4]) {
    __shared__ float As[64][33];
    __shared__ float Bs[32][65];
    int t = threadIdx.x;
    int tx = t & 15, ty = t >> 4;

    for (int k0 = 0; k0 < 256; k0 += 32) {
        int ra = t >> 2, ca = (t & 3) * 8;
#pragma unroll
        for (int q = 0; q < 8; q++) As[ra][ca + q] = A[(m0 + ra) * 256 + k0 + ca + q];
        int rb = t >> 3, cb = (t & 7) * 8;
#pragma unroll
        for (int q = 0; q < 8; q++) Bs[rb][cb + q] = Bm[(k0 + rb) * 256 + n0 + cb + q];
        __syncthreads();
#pragma unroll 8
        for (int kk = 0; kk < 32; kk++) {
            float a[4], bb[4];
#pragma unroll
            for (int ii = 0; ii < 4; ii++) a[ii] = As[ty * 4 + ii][kk];
#pragma unroll
            for (int jj = 0; jj < 4; jj++) bb[jj] = Bs[kk][tx * 4 + jj];
#pragma unroll
            for (int ii = 0; ii < 4; ii++)
#pragma unroll
                for (int jj = 0; jj < 4; jj++) acc[ii][jj] = fmaf(a[ii], bb[jj], acc[ii][jj]);
        }
        __syncthreads();
    }
}

// ---------------- Kernel 2: QKVG projections ----------------
__global__ __launch_bounds__(256) void gemm_qkvg_kernel(const float* __restrict__ Wq,
                                                        const float* __restrict__ bq,
                                                        const float* __restrict__ Wk,
                                                        const float* __restrict__ Wv,
                                                        const float* __restrict__ Wg) {
    const float* Bm;
    float* C;
    int mode;
    switch (blockIdx.z) {
        case 0: Bm = Wq; C = d_Q; mode = 1; break;
        case 1: Bm = Wk; C = d_K; mode = 0; break;
        case 2: Bm = Wv; C = d_V; mode = 0; break;
        default: Bm = Wg; C = d_G; mode = 2; break;
    }
    int m0 = blockIdx.x * 64, n0 = blockIdx.y * 64;
    float acc[4][4] = {};
    gemm_tile_64x64(d_sln, Bm, m0, n0, acc);

    int tx = threadIdx.x & 15, ty = threadIdx.x >> 4;
#pragma unroll
    for (int ii = 0; ii < 4; ii++)
#pragma unroll
        for (int jj = 0; jj < 4; jj++) {
            int mI = m0 + ty * 4 + ii, nI = n0 + tx * 4 + jj;
            float v = acc[ii][jj];
            if (mode == 1) v += bq[nI];
            if (mode == 2) v = 1.f / (1.f + __expf(-v));
            C[mI * 256 + nI] = v;
        }
}

// ---------------- Kernel 3: LayerNorm(z) fused with @Wb -> Bt[i][h][j] ----------------
// grid (1024, 8), 256 threads = 8 warps; each warp handles 16 (i,j) pairs,
// processing TWO rows per iteration (it, it+8) for MLP=2 and overlapped shuffle chains.
__global__ __launch_bounds__(256) void zln_bias_kernel(const float* __restrict__ z,
                                                       const float* __restrict__ gz,
                                                       const float* __restrict__ bz,
                                                       const float* __restrict__ Wb) {
    __shared__ float Wbs[CZ * NH];   // [c][h]
    __shared__ float gzs[CZ], bzs[CZ];
    __shared__ float sOut[NH * 132]; // padded stride 132

    int t = threadIdx.x;
    for (int idx = t; idx < CZ * NH; idx += 256) Wbs[idx] = Wb[idx];
    if (t < CZ) { gzs[t] = gz[t]; bzs[t] = bz[t]; }
    __syncthreads();

    int warp = t >> 5, lane = t & 31;
    int i = blockIdx.x;
    int jbase = blockIdx.y * 128;
    const float* zrow = z + ((size_t)i * L + jbase + warp * 16) * CZ + lane * 4;
    int head = ((lane >> 4) & 1) * 4 + ((lane >> 3) & 1) * 2 + ((lane >> 2) & 1);
    int c0 = lane * 4;
    float wv[8][4];
#pragma unroll
    for (int c = 0; c < 4; c++)
#pragma unroll
        for (int h = 0; h < 8; h++) wv[h][c] = Wbs[(c0 + c) * NH + h];
    float g4[4] = {gzs[c0], gzs[c0 + 1], gzs[c0 + 2], gzs[c0 + 3]};
    float b4[4] = {bzs[c0], bzs[c0 + 1], bzs[c0 + 2], bzs[c0 + 3]};

    for (int it = 0; it < 8; it++) {
        const float4 cx = *(const float4*)(zrow + (size_t)it * CZ);
        const float4 cy = *(const float4*)(zrow + (size_t)(it + 8) * CZ);

        float s1x = cx.x + cx.y + cx.z + cx.w;
        float s1y = cy.x + cy.y + cy.z + cy.w;
        float s2x = fmaf(cx.x, cx.x, fmaf(cx.y, cx.y, fmaf(cx.z, cx.z, cx.w * cx.w)));
        float s2y = fmaf(cy.x, cy.x, fmaf(cy.y, cy.y, fmaf(cy.z, cy.z, cy.w * cy.w)));
#pragma unroll
        for (int off = 16; off > 0; off >>= 1) {
            s1x += __shfl_xor_sync(0xffffffffu, s1x, off);
            s1y += __shfl_xor_sync(0xffffffffu, s1y, off);
            s2x += __shfl_xor_sync(0xffffffffu, s2x, off);
            s2y += __shfl_xor_sync(0xffffffffu, s2y, off);
        }
        float mx = s1x * (1.f / CZ), my = s1y * (1.f / CZ);
        float rx = rsqrtf(s2x * (1.f / CZ) - mx * mx + LN_EPS);
        float ry = rsqrtf(s2y * (1.f / CZ) - my * my + LN_EPS);

        float znx[4], zny[4];
        znx[0] = (cx.x - mx) * rx * g4[0] + b4[0];
        znx[1] = (cx.y - mx) * rx * g4[1] + b4[1];
        znx[2] = (cx.z - mx) * rx * g4[2] + b4[2];
        znx[3] = (cx.w - mx) * rx * g4[3] + b4[3];
        zny[0] = (cy.x - my) * ry * g4[0] + b4[0];
        zny[1] = (cy.y - my) * ry * g4[1] + b4[1];
        zny[2] = (cy.z - my) * ry * g4[2] + b4[2];
        zny[3] = (cy.w - my) * ry * g4[3] + b4[3];

        float ax[8] = {}, ay[8] = {};
#pragma unroll
        for (int c = 0; c < 4; c++)
#pragma unroll
            for (int h = 0; h < 8; h++) {
                ax[h] = fmaf(znx[c], wv[h][c], ax[h]);
                ay[h] = fmaf(zny[c], wv[h][c], ay[h]);
            }

        // folded reduce (both rows interleaved): 9 shuffles each
        bool hi16 = (lane & 16) != 0;
        float bx[4], by[4];
#pragma unroll
        for (int k = 0; k < 4; k++) {
            float sx = hi16 ? ax[k] : ax[k + 4];
            float sy = hi16 ? ay[k] : ay[k + 4];
            float rxx = __shfl_xor_sync(0xffffffffu, sx, 16);
            float ryy = __shfl_xor_sync(0xffffffffu, sy, 16);
            bx[k] = (hi16 ? ax[k + 4] : ax[k]) + rxx;
            by[k] = (hi16 ? ay[k + 4] : ay[k]) + ryy;
        }
        bool hi8 = (lane & 8) != 0;
        float ccx[2], ccy[2];
#pragma unroll
        for (int k = 0; k < 2; k++) {
            float sx = hi8 ? bx[k] : bx[k + 2];
            float sy = hi8 ? by[k] : by[k + 2];
            float rxx = __shfl_xor_sync(0xffffffffu, sx, 8);
            float ryy = __shfl_xor_sync(0xffffffffu, sy, 8);
            ccx[k] = (hi8 ? bx[k + 2] : bx[k]) + rxx;
            ccy[k] = (hi8 ? by[k + 2] : by[k]) + ryy;
        }
        bool hi4 = (lane & 4) != 0;
        float sx = hi4 ? ccx[0] : ccx[1];
        float sy = hi4 ? ccy[0] : ccy[1];
        float rxx = __shfl_xor_sync(0xffffffffu, sx, 4);
        float ryy = __shfl_xor_sync(0xffffffffu, sy, 4);
        float ddx = (hi4 ? ccx[1] : ccx[0]) + rxx;
        float ddy = (hi4 ? ccy[1] : ccy[0]) + ryy;
        ddx += __shfl_xor_sync(0xffffffffu, ddx, 2);
        ddy += __shfl_xor_sync(0xffffffffu, ddy, 2);
        ddx += __shfl_xor_sync(0xffffffffu, ddx, 1);
        ddy += __shfl_xor_sync(0xffffffffu, ddy, 1);
        if ((lane & 3) == 0) {
            sOut[head * 132 + warp * 16 + it] = ddx;
            sOut[head * 132 + warp * 16 + it + 8] = ddy;
        }
    }
    __syncthreads();

    int h = t >> 5, col = (t & 31) * 4;
    float4 v = *(const float4*)&sOut[h * 132 + col];
    *(float4*)&d_Bt[((size_t)i * NH + h) * L + jbase + col] = v;
}

// ---------------- Kernel 4a: split attention, BM=64 rows, 256 threads ----------------
__global__ __launch_bounds__(256) void attn_split_kernel(const int* __restrict__ mask) {
    __shared__ float Qs[BM][33];
    __shared__ float Ks[BN][33];
    __shared__ float Vs[BN][32];
    __shared__ float Ss[BM][67];
    __shared__ float row_m[BM], row_l[BM], row_alpha[BM];
    __shared__ unsigned char ms[BN];

    int t = threadIdx.x;
    int h = blockIdx.y;
    int i0 = blockIdx.x * BM;
    int split = blockIdx.z;
    int tx = t & 15, ty = t >> 4;

    // load Q pre-scaled (64 x 32)
#pragma unroll
    for (int rep = 0; rep < 2; rep++) {
        int idx = t + rep * 256;
        int r = idx >> 3, dgq = idx & 7;
        float4 q4 = *(const float4*)&d_Q[(i0 + r) * CS + h * DH + dgq * 4];
        Qs[r][dgq * 4 + 0] = q4.x * QK_SCALE;
        Qs[r][dgq * 4 + 1] = q4.y * QK_SCALE;
        Qs[r][dgq * 4 + 2] = q4.z * QK_SCALE;
        Qs[r][dgq * 4 + 3] = q4.w * QK_SCALE;
    }
    if (t < BM) { row_m[t] = -CUDART_INF_F; row_l[t] = 0.f; }

    // PV ownership: 2 rows x 4 d per thread
    int dg = t & 7;
    int r0 = (t >> 3) * 2;
    float4 O0 = make_float4(0.f, 0.f, 0.f, 0.f);
    float4 O1 = make_float4(0.f, 0.f, 0.f, 0.f);

    for (int jt = 0; jt < 4; jt++) {
        int j0 = split * 256 + jt * BN;
        __syncthreads();
        // load K/V tiles
#pragma unroll
        for (int rep = 0; rep < 2; rep++) {
            int idx = t + rep * 256;
            int r = idx >> 3, g = idx & 7;
            float4 k4 = *(const float4*)&d_K[(j0 + r) * CS + h * DH + g * 4];
            Ks[r][g * 4 + 0] = k4.x;
            Ks[r][g * 4 + 1] = k4.y;
            Ks[r][g * 4 + 2] = k4.z;
            Ks[r][g * 4 + 3] = k4.w;
            *(float4*)&Vs[r][g * 4] = *(const float4*)&d_V[(j0 + r) * CS + h * DH + g * 4];
        }
        if (t < BN) ms[t] = (unsigned char)(mask[j0 + t] != 0);
        __syncthreads();

        // S = Q K^T (64x64, 4x4 per thread)
        float sacc[4][4] = {};
#pragma unroll 8
        for (int d = 0; d < 32; d++) {
            float a[4], bb[4];
#pragma unroll
            for (int ii = 0; ii < 4; ii++) a[ii] = Qs[ty * 4 + ii][d];
#pragma unroll
            for (int jj = 0; jj < 4; jj++) bb[jj] = Ks[tx * 4 + jj][d];
#pragma unroll
            for (int ii = 0; ii < 4; ii++)
#pragma unroll
                for (int jj = 0; jj < 4; jj++) sacc[ii][jj] = fmaf(a[ii], bb[jj], sacc[ii][jj]);
        }
        // bias + mask + store S
#pragma unroll
        for (int ii = 0; ii < 4; ii++) {
            int iI = ty * 4 + ii;
            const float4 bv = *(const float4*)&d_Bt[(size_t)(i0 + iI) * (NH * L) + h * L + j0 + tx * 4];
            float bb4[4] = {bv.x, bv.y, bv.z, bv.w};
#pragma unroll
            for (int jj = 0; jj < 4; jj++) {
                int jl = tx * 4 + jj;
                Ss[iI][jl] = ms[jl] ? (sacc[ii][jj] + bb4[jj]) : -CUDART_INF_F;
            }
        }
        __syncthreads();

        // online softmax: rw = t>>2 (64 rows), gq = t&3 (16 j each)
        {
            int rw = t >> 2, gq = t & 3;
            float mold = row_m[rw];
            float mx = -CUDART_INF_F;
#pragma unroll
            for (int q = 0; q < 16; q++) mx = fmaxf(mx, Ss[rw][gq * 16 + q]);
            mx = fmaxf(mx, __shfl_xor_sync(0xffffffffu, mx, 1));
            mx = fmaxf(mx, __shfl_xor_sync(0xffffffffu, mx, 2));
            float nm = fmaxf(mold, mx);
            float alpha = (nm == -CUDART_INF_F) ? 1.f : __expf(mold - nm);
            float ps = 0.f;
#pragma unroll
            for (int q = 0; q < 16; q++) {
                float sv = Ss[rw][gq * 16 + q];
                float p = (sv == -CUDART_INF_F) ? 0.f : __expf(sv - nm);
                Ss[rw][gq * 16 + q] = p;
                ps += p;
            }
            ps += __shfl_xor_sync(0xffffffffu, ps, 1);
            ps += __shfl_xor_sync(0xffffffffu, ps, 2);
            if (gq == 0) {
                row_m[rw] = nm;
                row_l[rw] = row_l[rw] * alpha + ps;
                row_alpha[rw] = alpha;
            }
        }
        __syncthreads();

        // PV: O += P @ V, 2 rows x 4 d per thread
        {
            float a0 = row_alpha[r0], a1 = row_alpha[r0 + 1];
            O0.x *= a0; O0.y *= a0; O0.z *= a0; O0.w *= a0;
            O1.x *= a1; O1.y *= a1; O1.z *= a1; O1.w *= a1;
#pragma unroll 4
            for (int j = 0; j < BN; j++) {
                float p0 = Ss[r0][j];
                float p1 = Ss[r0 + 1][j];
                const float4 v = *(const float4*)&Vs[j][dg * 4];
                O0.x = fmaf(p0, v.x, O0.x);
                O0.y = fmaf(p0, v.y, O0.y);
                O0.z = fmaf(p0, v.z, O0.z);
                O0.w = fmaf(p0, v.w, O0.w);
                O1.x = fmaf(p1, v.x, O1.x);
                O1.y = fmaf(p1, v.y, O1.y);
                O1.z = fmaf(p1, v.z, O1.z);
                O1.w = fmaf(p1, v.w, O1.w);
            }
        }
    }

    // write partials (unnormalized O and per-row m,l)
    {
        size_t b0 = (((size_t)(split * NH + h)) * L + i0 + r0) * DH + dg * 4;
        *(float4*)&d_pO[b0] = O0;
        *(float4*)&d_pO[b0 + DH] = O1;
        if (t < BM) d_pml[((split * NH + h) * L) + i0 + t] = make_float2(row_m[t], row_l[t]);
    }
}

// ---------------- Kernel 4b: combine splits, apply 1/l and G gate ----------------
__global__ __launch_bounds__(256) void attn_combine_kernel() {
    int t = threadIdx.x;
    int i = blockIdx.x;
    int h = t >> 5, lane = t & 31;

    float2 ml[NSPLIT];
    float mx = -CUDART_INF_F;
#pragma unroll
    for (int s = 0; s < NSPLIT; s++) {
        ml[s] = d_pml[((s * NH + h) * L) + i];
        mx = fmaxf(mx, ml[s].x);
    }
    float lsum = 0.f, o = 0.f;
#pragma unroll
    for (int s = 0; s < NSPLIT; s++) {
        float w = (ml[s].x == -CUDART_INF_F) ? 0.f : __expf(ml[s].x - mx);
        lsum = fmaf(ml[s].y, w, lsum);
        o = fmaf(d_pO[(((s * NH + h) * L) + i) * DH + lane], w, o);
    }
    float rl = (lsum > 0.f) ? (1.f / lsum) : 0.f;
    int base = i * CS + h * DH + lane;
    d_AO[base] = o * rl * d_G[base];
}

// ---------------- Kernel 5: ds = (G*out) @ Wo * mask ----------------
__global__ __launch_bounds__(256) void gemm_out_kernel(const float* __restrict__ Wo,
                                                       const int* __restrict__ mask,
                                                       float* __restrict__ out) {
    int m0 = blockIdx.x * 64, n0 = blockIdx.y * 64;
    float acc[4][4] = {};
    gemm_tile_64x64(d_AO, Wo, m0, n0, acc);

    int tx = threadIdx.x & 15, ty = threadIdx.x >> 4;
#pragma unroll
    for (int ii = 0; ii < 4; ii++) {
        int mI = m0 + ty * 4 + ii;
        float mk = (mask[mI] != 0) ? 1.f : 0.f;
#pragma unroll
        for (int jj = 0; jj < 4; jj++) {
            int nI = n0 + tx * 4 + jj;
            out[mI * 256 + nI] = acc[ii][jj] * mk;
        }
    }
}

// ---------------- launch ----------------
extern "C" void kernel_launch(void* const* d_in, const int* in_sizes, int n_in,
                              void* d_out, int out_size) {
    const float* s = (const float*)d_in[0];
    const float* z = (const float*)d_in[1];
    const int* res_mask = (const int*)d_in[2];
    const float* g_s = (const float*)d_in[3];
    const float* b_s = (const float*)d_in[4];
    const float* g_z = (const float*)d_in[5];
    const float* b_z = (const float*)d_in[6];
    const float* Wq = (const float*)d_in[7];
    const float* bq = (const float*)d_in[8];
    const float* Wk = (const float*)d_in[9];
    const float* Wv = (const float*)d_in[10];
    const float* Wb = (const float*)d_in[11];
    const float* Wg = (const float*)d_in[12];
    const float* Wo = (const float*)d_in[13];
    float* out = (float*)d_out;

    ln_s_kernel<<<L, 256>>>(s, g_s, b_s);
    gemm_qkvg_kernel<<<dim3(16, 4, 4), 256>>>(Wq, bq, Wk, Wv, Wg);
    zln_bias_kernel<<<dim3(L, 8), 256>>>(z, g_z, b_z, Wb);
    attn_split_kernel<<<dim3(16, 8, NSPLIT), 256>>>(res_mask);
    attn_combine_kernel<<<L, 256>>>();
    gemm_out_kernel<<<dim3(16, 4), 256>>>(Wo, res_mask, out);
}

// round 5
// speedup vs baseline: 1.2123x; 1.2123x over previous
#include <cuda_runtime.h>
#include <math_constants.h>

#define L 1024
#define CS 256
#define CZ 128
#define NH 8
#define DH 32
#define NSPLIT 4
#define BM 64
#define BN 64
#define LN_EPS 1e-5f
#define QK_SCALE 0.17677669529663687f  // 1/sqrt(32)

// ---------------- scratch (device globals; no allocation allowed) ----------------
__device__ float d_sln[L * CS];
__device__ float d_Q[L * CS];
__device__ float d_K[L * CS];
__device__ float d_V[L * CS];
__device__ float d_G[L * CS];
__device__ float d_Bt[(size_t)L * NH * L];             // bias transposed: [i][h][j], 32 MB
__device__ float d_AO[L * CS];                         // G * attn_out
__device__ float d_pO[NSPLIT * NH * L * DH];           // split attention partial O
__device__ float2 d_pml[NSPLIT * NH * L];              // split attention partial (m, l)

// ---------------- Kernel 1: LayerNorm(s) ----------------
__global__ __launch_bounds__(256) void ln_s_kernel(const float* __restrict__ s,
                                                   const float* __restrict__ g,
                                                   const float* __restrict__ b) {
    int r = blockIdx.x, t = threadIdx.x;
    float v = s[r * CS + t];
    __shared__ float red[8];

    float sum = v;
#pragma unroll
    for (int off = 16; off > 0; off >>= 1) sum += __shfl_xor_sync(0xffffffffu, sum, off);
    if ((t & 31) == 0) red[t >> 5] = sum;
    __syncthreads();
    float tot = 0.f;
#pragma unroll
    for (int k = 0; k < 8; k++) tot += red[k];
    float mean = tot * (1.f / CS);
    float d = v - mean;
    __syncthreads();

    float sq = d * d;
#pragma unroll
    for (int off = 16; off > 0; off >>= 1) sq += __shfl_xor_sync(0xffffffffu, sq, off);
    if ((t & 31) == 0) red[t >> 5] = sq;
    __syncthreads();
    float tot2 = 0.f;
#pragma unroll
    for (int k = 0; k < 8; k++) tot2 += red[k];
    float rstd = rsqrtf(tot2 * (1.f / CS) + LN_EPS);

    d_sln[r * CS + t] = d * rstd * g[t] + b[t];
}

// ---------------- shared GEMM tile helper: C[64x64] tile of (A[1024x256] @ B[256x256]) ----------------
__device__ __forceinline__ void gemm_tile_64x64(const float* __restrict__ A,
                                                const float* __restrict__ Bm,
                                                int m0, int n0, float acc[4][4]) {
    __shared__ float As[64][33];
    __shared__ float Bs[32][65];
    int t = threadIdx.x;
    int tx = t & 15, ty = t >> 4;

    for (int k0 = 0; k0 < 256; k0 += 32) {
        int ra = t >> 2, ca = (t & 3) * 8;
#pragma unroll
        for (int q = 0; q < 8; q++) As[ra][ca + q] = A[(m0 + ra) * 256 + k0 + ca + q];
        int rb = t >> 3, cb = (t & 7) * 8;
#pragma unroll
        for (int q = 0; q < 8; q++) Bs[rb][cb + q] = Bm[(k0 + rb) * 256 + n0 + cb + q];
        __syncthreads();
#pragma unroll 8
        for (int kk = 0; kk < 32; kk++) {
            float a[4], bb[4];
#pragma unroll
            for (int ii = 0; ii < 4; ii++) a[ii] = As[ty * 4 + ii][kk];
#pragma unroll
            for (int jj = 0; jj < 4; jj++) bb[jj] = Bs[kk][tx * 4 + jj];
#pragma unroll
            for (int ii = 0; ii < 4; ii++)
#pragma unroll
                for (int jj = 0; jj < 4; jj++) acc[ii][jj] = fmaf(a[ii], bb[jj], acc[ii][jj]);
        }
        __syncthreads();
    }
}

// ---------------- Kernel 2: QKVG projections ----------------
__global__ __launch_bounds__(256) void gemm_qkvg_kernel(const float* __restrict__ Wq,
                                                        const float* __restrict__ bq,
                                                        const float* __restrict__ Wk,
                                                        const float* __restrict__ Wv,
                                                        const float* __restrict__ Wg) {
    const float* Bm;
    float* C;
    int mode;
    switch (blockIdx.z) {
        case 0: Bm = Wq; C = d_Q; mode = 1; break;
        case 1: Bm = Wk; C = d_K; mode = 0; break;
        case 2: Bm = Wv; C = d_V; mode = 0; break;
        default: Bm = Wg; C = d_G; mode = 2; break;
    }
    int m0 = blockIdx.x * 64, n0 = blockIdx.y * 64;
    float acc[4][4] = {};
    gemm_tile_64x64(d_sln, Bm, m0, n0, acc);

    int tx = threadIdx.x & 15, ty = threadIdx.x >> 4;
#pragma unroll
    for (int ii = 0; ii < 4; ii++)
#pragma unroll
        for (int jj = 0; jj < 4; jj++) {
            int mI = m0 + ty * 4 + ii, nI = n0 + tx * 4 + jj;
            float v = acc[ii][jj];
            if (mode == 1) v += bq[nI];
            if (mode == 2) v = 1.f / (1.f + __expf(-v));
            C[mI * 256 + nI] = v;
        }
}

// ---------------- Kernel 3: LayerNorm(z) fused with @Wb -> Bt[i][h][j] (v3: no shuffles) ----------------
// Identity: sum_c zn_c W[c,h] = rstd*(sum_c v_c*gW[c,h]) - rstd*mean*SgW[h] + SbW[h]
// Block = one i, 64 j. Thread (r, q): r = row (j), q = quarter of c. 8x float4 LDG (MLP=8),
// partial dots vs smem GW (broadcast, conflict-free), 4-thread smem combine. No warp shuffles.
__global__ __launch_bounds__(256) void zln_bias_kernel(const float* __restrict__ z,
                                                       const float* __restrict__ gz,
                                                       const float* __restrict__ bz,
                                                       const float* __restrict__ Wb) {
    __shared__ float Wbs[CZ * NH];       // [c][h]
    __shared__ float gzs[CZ], bzs[CZ];
    __shared__ float4 GW4[4][65];        // [q][h*8+k]  (65-pad: q-stride 1040B -> distinct banks)
    __shared__ float SgW[NH], SbW[NH];
    __shared__ float pP[64 * 37];        // partial head sums [r][q*9+h]
    __shared__ float2 psum[64][4];       // partial (s1, s2) [r][q]
    __shared__ float sB[NH * 68];        // staged output [h][r]

    int t = threadIdx.x;
    int i = blockIdx.y;
    int jbase = blockIdx.x * 64;

    // prep: raw params to smem
    for (int idx = t; idx < CZ * NH; idx += 256) Wbs[idx] = Wb[idx];
    if (t < CZ) { gzs[t] = gz[t]; bzs[t] = bz[t]; }
    __syncthreads();

    // build GW4[q][h*8+k] = g[c..c+3] * W[c..c+3][h], c = q*32 + k*4
    {
        int q = t >> 6, rem = t & 63, h = rem >> 3, k = rem & 7;
        int c = q * 32 + k * 4;
        GW4[q][h * 8 + k] = make_float4(gzs[c] * Wbs[c * NH + h],
                                        gzs[c + 1] * Wbs[(c + 1) * NH + h],
                                        gzs[c + 2] * Wbs[(c + 2) * NH + h],
                                        gzs[c + 3] * Wbs[(c + 3) * NH + h]);
    }
    if (t < 16) {
        int h = t & 7;
        float acc = 0.f;
        if (t < 8) {
            for (int c = 0; c < CZ; c++) acc = fmaf(gzs[c], Wbs[c * NH + h], acc);
            SgW[h] = acc;
        } else {
            for (int c = 0; c < CZ; c++) acc = fmaf(bzs[c], Wbs[c * NH + h], acc);
            SbW[h] = acc;
        }
    }
    __syncthreads();

    // main: per-thread partial dots over 32 c's
    {
        int r = t >> 2, q = t & 3;
        const float4* zp = (const float4*)(z + ((size_t)i * L + jbase + r) * CZ) + q * 8;
        float4 zv[8];
#pragma unroll
        for (int k = 0; k < 8; k++) zv[k] = zp[k];

        float s1 = 0.f, s2 = 0.f;
        float pa[8] = {};
#pragma unroll
        for (int k = 0; k < 8; k++) {
            float4 v = zv[k];
#pragma unroll
            for (int h = 0; h < 8; h++) {
                float4 w = GW4[q][h * 8 + k];
                pa[h] = fmaf(v.x, w.x, pa[h]);
                pa[h] = fmaf(v.y, w.y, pa[h]);
                pa[h] = fmaf(v.z, w.z, pa[h]);
                pa[h] = fmaf(v.w, w.w, pa[h]);
            }
            s1 += v.x + v.y + v.z + v.w;
            s2 = fmaf(v.x, v.x, fmaf(v.y, v.y, fmaf(v.z, v.z, fmaf(v.w, v.w, s2))));
        }
#pragma unroll
        for (int h = 0; h < 8; h++) pP[r * 37 + q * 9 + h] = pa[h];
        psum[r][q] = make_float2(s1, s2);
    }
    __syncthreads();

    // combine: thread (r, hp) finishes heads hp and hp+4
    {
        int r = t >> 2, hp = t & 3;
        float2 p0 = psum[r][0], p1 = psum[r][1], p2 = psum[r][2], p3 = psum[r][3];
        float s1 = p0.x + p1.x + p2.x + p3.x;
        float s2 = p0.y + p1.y + p2.y + p3.y;
        float mean = s1 * (1.f / CZ);
        float rstd = rsqrtf(s2 * (1.f / CZ) - mean * mean + LN_EPS);
        float mr = mean * rstd;

        float a0 = pP[r * 37 + 0 * 9 + hp] + pP[r * 37 + 1 * 9 + hp] +
                   pP[r * 37 + 2 * 9 + hp] + pP[r * 37 + 3 * 9 + hp];
        float a1 = pP[r * 37 + 0 * 9 + hp + 4] + pP[r * 37 + 1 * 9 + hp + 4] +
                   pP[r * 37 + 2 * 9 + hp + 4] + pP[r * 37 + 3 * 9 + hp + 4];
        sB[hp * 68 + r] = rstd * a0 - mr * SgW[hp] + SbW[hp];
        sB[(hp + 4) * 68 + r] = rstd * a1 - mr * SgW[hp + 4] + SbW[hp + 4];
    }
    __syncthreads();

    // coalesced write: 8 heads x 64 j = 128 float4
    if (t < 128) {
        int h = t >> 4, col = (t & 15) * 4;
        float4 v = *(const float4*)&sB[h * 68 + col];
        *(float4*)&d_Bt[((size_t)i * NH + h) * L + jbase + col] = v;
    }
}

// ---------------- Kernel 4a: split attention, BM=64 rows, 256 threads ----------------
__global__ __launch_bounds__(256) void attn_split_kernel(const int* __restrict__ mask) {
    __shared__ float Qs[BM][33];
    __shared__ float Ks[BN][33];
    __shared__ float Vs[BN][32];
    __shared__ float Ss[BM][67];
    __shared__ float row_m[BM], row_l[BM], row_alpha[BM];
    __shared__ unsigned char ms[BN];

    int t = threadIdx.x;
    int h = blockIdx.y;
    int i0 = blockIdx.x * BM;
    int split = blockIdx.z;
    int tx = t & 15, ty = t >> 4;

    // load Q pre-scaled (64 x 32)
#pragma unroll
    for (int rep = 0; rep < 2; rep++) {
        int idx = t + rep * 256;
        int r = idx >> 3, dgq = idx & 7;
        float4 q4 = *(const float4*)&d_Q[(i0 + r) * CS + h * DH + dgq * 4];
        Qs[r][dgq * 4 + 0] = q4.x * QK_SCALE;
        Qs[r][dgq * 4 + 1] = q4.y * QK_SCALE;
        Qs[r][dgq * 4 + 2] = q4.z * QK_SCALE;
        Qs[r][dgq * 4 + 3] = q4.w * QK_SCALE;
    }
    if (t < BM) { row_m[t] = -CUDART_INF_F; row_l[t] = 0.f; }

    // PV ownership: 2 rows x 4 d per thread
    int dg = t & 7;
    int r0 = (t >> 3) * 2;
    float4 O0 = make_float4(0.f, 0.f, 0.f, 0.f);
    float4 O1 = make_float4(0.f, 0.f, 0.f, 0.f);

    for (int jt = 0; jt < 4; jt++) {
        int j0 = split * 256 + jt * BN;
        __syncthreads();
        // load K/V tiles
#pragma unroll
        for (int rep = 0; rep < 2; rep++) {
            int idx = t + rep * 256;
            int r = idx >> 3, g = idx & 7;
            float4 k4 = *(const float4*)&d_K[(j0 + r) * CS + h * DH + g * 4];
            Ks[r][g * 4 + 0] = k4.x;
            Ks[r][g * 4 + 1] = k4.y;
            Ks[r][g * 4 + 2] = k4.z;
            Ks[r][g * 4 + 3] = k4.w;
            *(float4*)&Vs[r][g * 4] = *(const float4*)&d_V[(j0 + r) * CS + h * DH + g * 4];
        }
        if (t < BN) ms[t] = (unsigned char)(mask[j0 + t] != 0);
        __syncthreads();

        // S = Q K^T (64x64, 4x4 per thread)
        float sacc[4][4] = {};
#pragma unroll 8
        for (int d = 0; d < 32; d++) {
            float a[4], bb[4];
#pragma unroll
            for (int ii = 0; ii < 4; ii++) a[ii] = Qs[ty * 4 + ii][d];
#pragma unroll
            for (int jj = 0; jj < 4; jj++) bb[jj] = Ks[tx * 4 + jj][d];
#pragma unroll
            for (int ii = 0; ii < 4; ii++)
#pragma unroll
                for (int jj = 0; jj < 4; jj++) sacc[ii][jj] = fmaf(a[ii], bb[jj], sacc[ii][jj]);
        }
        // bias + mask + store S
#pragma unroll
        for (int ii = 0; ii < 4; ii++) {
            int iI = ty * 4 + ii;
            const float4 bv = *(const float4*)&d_Bt[(size_t)(i0 + iI) * (NH * L) + h * L + j0 + tx * 4];
            float bb4[4] = {bv.x, bv.y, bv.z, bv.w};
#pragma unroll
            for (int jj = 0; jj < 4; jj++) {
                int jl = tx * 4 + jj;
                Ss[iI][jl] = ms[jl] ? (sacc[ii][jj] + bb4[jj]) : -CUDART_INF_F;
            }
        }
        __syncthreads();

        // online softmax: rw = t>>2 (64 rows), gq = t&3 (16 j each)
        {
            int rw = t >> 2, gq = t & 3;
            float mold = row_m[rw];
            float mx = -CUDART_INF_F;
#pragma unroll
            for (int q = 0; q < 16; q++) mx = fmaxf(mx, Ss[rw][gq * 16 + q]);
            mx = fmaxf(mx, __shfl_xor_sync(0xffffffffu, mx, 1));
            mx = fmaxf(mx, __shfl_xor_sync(0xffffffffu, mx, 2));
            float nm = fmaxf(mold, mx);
            float alpha = (nm == -CUDART_INF_F) ? 1.f : __expf(mold - nm);
            float ps = 0.f;
#pragma unroll
            for (int q = 0; q < 16; q++) {
                float sv = Ss[rw][gq * 16 + q];
                float p = (sv == -CUDART_INF_F) ? 0.f : __expf(sv - nm);
                Ss[rw][gq * 16 + q] = p;
                ps += p;
            }
            ps += __shfl_xor_sync(0xffffffffu, ps, 1);
            ps += __shfl_xor_sync(0xffffffffu, ps, 2);
            if (gq == 0) {
                row_m[rw] = nm;
                row_l[rw] = row_l[rw] * alpha + ps;
                row_alpha[rw] = alpha;
            }
        }
        __syncthreads();

        // PV: O += P @ V, 2 rows x 4 d per thread
        {
            float a0 = row_alpha[r0], a1 = row_alpha[r0 + 1];
            O0.x *= a0; O0.y *= a0; O0.z *= a0; O0.w *= a0;
            O1.x *= a1; O1.y *= a1; O1.z *= a1; O1.w *= a1;
#pragma unroll 4
            for (int j = 0; j < BN; j++) {
                float p0 = Ss[r0][j];
                float p1 = Ss[r0 + 1][j];
                const float4 v = *(const float4*)&Vs[j][dg * 4];
                O0.x = fmaf(p0, v.x, O0.x);
                O0.y = fmaf(p0, v.y, O0.y);
                O0.z = fmaf(p0, v.z, O0.z);
                O0.w = fmaf(p0, v.w, O0.w);
                O1.x = fmaf(p1, v.x, O1.x);
                O1.y = fmaf(p1, v.y, O1.y);
                O1.z = fmaf(p1, v.z, O1.z);
                O1.w = fmaf(p1, v.w, O1.w);
            }
        }
    }

    // write partials (unnormalized O and per-row m,l)
    {
        size_t b0 = (((size_t)(split * NH + h)) * L + i0 + r0) * DH + dg * 4;
        *(float4*)&d_pO[b0] = O0;
        *(float4*)&d_pO[b0 + DH] = O1;
        if (t < BM) d_pml[((split * NH + h) * L) + i0 + t] = make_float2(row_m[t], row_l[t]);
    }
}

// ---------------- Kernel 4b: combine splits, apply 1/l and G gate ----------------
__global__ __launch_bounds__(256) void attn_combine_kernel() {
    int t = threadIdx.x;
    int i = blockIdx.x;
    int h = t >> 5, lane = t & 31;

    float2 ml[NSPLIT];
    float mx = -CUDART_INF_F;
#pragma unroll
    for (int s = 0; s < NSPLIT; s++) {
        ml[s] = d_pml[((s * NH + h) * L) + i];
        mx = fmaxf(mx, ml[s].x);
    }
    float lsum = 0.f, o = 0.f;
#pragma unroll
    for (int s = 0; s < NSPLIT; s++) {
        float w = (ml[s].x == -CUDART_INF_F) ? 0.f : __expf(ml[s].x - mx);
        lsum = fmaf(ml[s].y, w, lsum);
        o = fmaf(d_pO[(((s * NH + h) * L) + i) * DH + lane], w, o);
    }
    float rl = (lsum > 0.f) ? (1.f / lsum) : 0.f;
    int base = i * CS + h * DH + lane;
    d_AO[base] = o * rl * d_G[base];
}

// ---------------- Kernel 5: ds = (G*out) @ Wo * mask ----------------
__global__ __launch_bounds__(256) void gemm_out_kernel(const float* __restrict__ Wo,
                                                       const int* __restrict__ mask,
                                                       float* __restrict__ out) {
    int m0 = blockIdx.x * 64, n0 = blockIdx.y * 64;
    float acc[4][4] = {};
    gemm_tile_64x64(d_AO, Wo, m0, n0, acc);

    int tx = threadIdx.x & 15, ty = threadIdx.x >> 4;
#pragma unroll
    for (int ii = 0; ii < 4; ii++) {
        int mI = m0 + ty * 4 + ii;
        float mk = (mask[mI] != 0) ? 1.f : 0.f;
#pragma unroll
        for (int jj = 0; jj < 4; jj++) {
            int nI = n0 + tx * 4 + jj;
            out[mI * 256 + nI] = acc[ii][jj] * mk;
        }
    }
}

// ---------------- launch ----------------
extern "C" void kernel_launch(void* const* d_in, const int* in_sizes, int n_in,
                              void* d_out, int out_size) {
    const float* s = (const float*)d_in[0];
    const float* z = (const float*)d_in[1];
    const int* res_mask = (const int*)d_in[2];
    const float* g_s = (const float*)d_in[3];
    const float* b_s = (const float*)d_in[4];
    const float* g_z = (const float*)d_in[5];
    const float* b_z = (const float*)d_in[6];
    const float* Wq = (const float*)d_in[7];
    const float* bq = (const float*)d_in[8];
    const float* Wk = (const float*)d_in[9];
    const float* Wv = (const float*)d_in[10];
    const float* Wb = (const float*)d_in[11];
    const float* Wg = (const float*)d_in[12];
    const float* Wo = (const float*)d_in[13];
    float* out = (float*)d_out;

    ln_s_kernel<<<L, 256>>>(s, g_s, b_s);
    gemm_qkvg_kernel<<<dim3(16, 4, 4), 256>>>(Wq, bq, Wk, Wv, Wg);
    zln_bias_kernel<<<dim3(16, L), 256>>>(z, g_z, b_z, Wb);
    attn_split_kernel<<<dim3(16, 8, NSPLIT), 256>>>(res_mask);
    attn_combine_kernel<<<L, 256>>>();
    gemm_out_kernel<<<dim3(16, 4), 256>>>(Wo, res_mask, out);
}

// round 6
// speedup vs baseline: 1.3246x; 1.0926x over previous
#include <cuda_runtime.h>
#include <math_constants.h>

#define L 1024
#define CS 256
#define CZ 128
#define NH 8
#define DH 32
#define NSPLIT 4
#define BM 64
#define BN 64
#define LN_EPS 1e-5f
#define QK_SCALE 0.17677669529663687f  // 1/sqrt(32)

// ---------------- scratch (device globals; no allocation allowed) ----------------
__device__ float d_sln[L * CS];
__device__ float d_Q[L * CS];
__device__ float d_K[L * CS];
__device__ float d_V[L * CS];
__device__ float d_G[L * CS];
__device__ float d_Bt[(size_t)L * NH * L];             // bias transposed: [i][h][j], 32 MB
__device__ float d_AO[L * CS];                         // G * attn_out
__device__ float d_pO[NSPLIT * NH * L * DH];           // split attention partial O
__device__ float2 d_pml[NSPLIT * NH * L];              // split attention partial (m, l)

// ---------------- Kernel 1: LayerNorm(s) ----------------
__global__ __launch_bounds__(256) void ln_s_kernel(const float* __restrict__ s,
                                                   const float* __restrict__ g,
                                                   const float* __restrict__ b) {
    int r = blockIdx.x, t = threadIdx.x;
    float v = s[r * CS + t];
    __shared__ float red[8];

    float sum = v;
#pragma unroll
    for (int off = 16; off > 0; off >>= 1) sum += __shfl_xor_sync(0xffffffffu, sum, off);
    if ((t & 31) == 0) red[t >> 5] = sum;
    __syncthreads();
    float tot = 0.f;
#pragma unroll
    for (int k = 0; k < 8; k++) tot += red[k];
    float mean = tot * (1.f / CS);
    float d = v - mean;
    __syncthreads();

    float sq = d * d;
#pragma unroll
    for (int off = 16; off > 0; off >>= 1) sq += __shfl_xor_sync(0xffffffffu, sq, off);
    if ((t & 31) == 0) red[t >> 5] = sq;
    __syncthreads();
    float tot2 = 0.f;
#pragma unroll
    for (int k = 0; k < 8; k++) tot2 += red[k];
    float rstd = rsqrtf(tot2 * (1.f / CS) + LN_EPS);

    d_sln[r * CS + t] = d * rstd * g[t] + b[t];
}

// ---------------- shared GEMM tile helper: C[64x64] tile of (A[1024x256] @ B[256x256]) ----------------
__device__ __forceinline__ void gemm_tile_64x64(const float* __restrict__ A,
                                                const float* __restrict__ Bm,
                                                int m0, int n0, float acc[4][4]) {
    __shared__ float As[64][33];
    __shared__ float Bs[32][65];
    int t = threadIdx.x;
    int tx = t & 15, ty = t >> 4;

    for (int k0 = 0; k0 < 256; k0 += 32) {
        int ra = t >> 2, ca = (t & 3) * 8;
#pragma unroll
        for (int q = 0; q < 8; q++) As[ra][ca + q] = A[(m0 + ra) * 256 + k0 + ca + q];
        int rb = t >> 3, cb = (t & 7) * 8;
#pragma unroll
        for (int q = 0; q < 8; q++) Bs[rb][cb + q] = Bm[(k0 + rb) * 256 + n0 + cb + q];
        __syncthreads();
#pragma unroll 8
        for (int kk = 0; kk < 32; kk++) {
            float a[4], bb[4];
#pragma unroll
            for (int ii = 0; ii < 4; ii++) a[ii] = As[ty * 4 + ii][kk];
#pragma unroll
            for (int jj = 0; jj < 4; jj++) bb[jj] = Bs[kk][tx * 4 + jj];
#pragma unroll
            for (int ii = 0; ii < 4; ii++)
#pragma unroll
                for (int jj = 0; jj < 4; jj++) acc[ii][jj] = fmaf(a[ii], bb[jj], acc[ii][jj]);
        }
        __syncthreads();
    }
}

// ---------------- Kernel 2: QKVG projections ----------------
__global__ __launch_bounds__(256) void gemm_qkvg_kernel(const float* __restrict__ Wq,
                                                        const float* __restrict__ bq,
                                                        const float* __restrict__ Wk,
                                                        const float* __restrict__ Wv,
                                                        const float* __restrict__ Wg) {
    const float* Bm;
    float* C;
    int mode;
    switch (blockIdx.z) {
        case 0: Bm = Wq; C = d_Q; mode = 1; break;
        case 1: Bm = Wk; C = d_K; mode = 0; break;
        case 2: Bm = Wv; C = d_V; mode = 0; break;
        default: Bm = Wg; C = d_G; mode = 2; break;
    }
    int m0 = blockIdx.x * 64, n0 = blockIdx.y * 64;
    float acc[4][4] = {};
    gemm_tile_64x64(d_sln, Bm, m0, n0, acc);

    int tx = threadIdx.x & 15, ty = threadIdx.x >> 4;
#pragma unroll
    for (int ii = 0; ii < 4; ii++)
#pragma unroll
        for (int jj = 0; jj < 4; jj++) {
            int mI = m0 + ty * 4 + ii, nI = n0 + tx * 4 + jj;
            float v = acc[ii][jj];
            if (mode == 1) v += bq[nI];
            if (mode == 2) v = 1.f / (1.f + __expf(-v));
            C[mI * 256 + nI] = v;
        }
}

// ---------------- Kernel 3: LayerNorm(z) fused with @Wb -> Bt[i][h][j] (v4) ----------------
// v3 compute (shuffle-free identity) + smem-staged z with swizzled conflict-free layout:
//   LDG: coalesced float4 (warp = 512B contiguous, nL=4)
//   zs slot(r, c4) = c4*64 + (r&56) + ((r + 2*(c4>>3) + (c4&7)) & 7)   [phase-verified]
// Phase-2 buffers alias the zs region (sync-separated).
struct ZPhase2 {
    float pP[64 * 37];
    float2 psum[64][4];
    float sB[NH * 68];
};
union ZUnion {
    float4 zs4[2048];   // 32 KB staging
    ZPhase2 p2;         // 13.7 KB, used after zs consumed
};

__global__ __launch_bounds__(256) void zln_bias_kernel(const float* __restrict__ z,
                                                       const float* __restrict__ gz,
                                                       const float* __restrict__ bz,
                                                       const float* __restrict__ Wb) {
    __shared__ ZUnion u;
    __shared__ float Wbs[CZ * NH];       // [c][h]
    __shared__ float gzs[CZ], bzs[CZ];
    __shared__ float4 GW4[4][65];        // [q][h*8+k]
    __shared__ float SgW[NH], SbW[NH];

    int t = threadIdx.x;
    int i = blockIdx.y;
    int jbase = blockIdx.x * 64;

    // phase 0: params to smem + coalesced z staging
    for (int idx = t; idx < CZ * NH; idx += 256) Wbs[idx] = Wb[idx];
    if (t < CZ) { gzs[t] = gz[t]; bzs[t] = bz[t]; }
    {
        const float4* zg = (const float4*)(z + ((size_t)i * L + jbase) * CZ);
#pragma unroll
        for (int p = 0; p < 8; p++) {
            int f = t + p * 256;          // 0..2047
            int r = f >> 5, c4 = f & 31;
            int slot = c4 * 64 + (r & 56) + ((r + 2 * (c4 >> 3) + (c4 & 7)) & 7);
            u.zs4[slot] = zg[f];
        }
    }
    __syncthreads();

    // phase 1: consume zs into registers; build GW4; SgW/SbW
    int r = t >> 2, q = t & 3;
    float4 zv[8];
#pragma unroll
    for (int k = 0; k < 8; k++) {
        int c4 = q * 8 + k;
        int slot = c4 * 64 + (r & 56) + ((r + 2 * q + k) & 7);
        zv[k] = u.zs4[slot];
    }
    {
        int qq = t >> 6, rem = t & 63, h = rem >> 3, k = rem & 7;
        int c = qq * 32 + k * 4;
        GW4[qq][h * 8 + k] = make_float4(gzs[c] * Wbs[c * NH + h],
                                         gzs[c + 1] * Wbs[(c + 1) * NH + h],
                                         gzs[c + 2] * Wbs[(c + 2) * NH + h],
                                         gzs[c + 3] * Wbs[(c + 3) * NH + h]);
    }
    if (t < 16) {
        int h = t & 7;
        float acc = 0.f;
        if (t < 8) {
            for (int c = 0; c < CZ; c++) acc = fmaf(gzs[c], Wbs[c * NH + h], acc);
            SgW[h] = acc;
        } else {
            for (int c = 0; c < CZ; c++) acc = fmaf(bzs[c], Wbs[c * NH + h], acc);
            SbW[h] = acc;
        }
    }
    __syncthreads();   // zs fully consumed; GW4 ready; p2 aliasing now safe

    // phase 2: partial dots
    {
        float s1 = 0.f, s2 = 0.f;
        float pa[8] = {};
#pragma unroll
        for (int k = 0; k < 8; k++) {
            float4 v = zv[k];
#pragma unroll
            for (int h = 0; h < 8; h++) {
                float4 w = GW4[q][h * 8 + k];
                pa[h] = fmaf(v.x, w.x, pa[h]);
                pa[h] = fmaf(v.y, w.y, pa[h]);
                pa[h] = fmaf(v.z, w.z, pa[h]);
                pa[h] = fmaf(v.w, w.w, pa[h]);
            }
            s1 += v.x + v.y + v.z + v.w;
            s2 = fmaf(v.x, v.x, fmaf(v.y, v.y, fmaf(v.z, v.z, fmaf(v.w, v.w, s2))));
        }
#pragma unroll
        for (int h = 0; h < 8; h++) u.p2.pP[r * 37 + q * 9 + h] = pa[h];
        u.p2.psum[r][q] = make_float2(s1, s2);
    }
    __syncthreads();

    // phase 3: combine per row, finish two heads per thread
    {
        int rr = t >> 2, hp = t & 3;
        float2 p0 = u.p2.psum[rr][0], p1 = u.p2.psum[rr][1];
        float2 p2v = u.p2.psum[rr][2], p3 = u.p2.psum[rr][3];
        float s1 = p0.x + p1.x + p2v.x + p3.x;
        float s2 = p0.y + p1.y + p2v.y + p3.y;
        float mean = s1 * (1.f / CZ);
        float rstd = rsqrtf(s2 * (1.f / CZ) - mean * mean + LN_EPS);
        float mr = mean * rstd;

        float a0 = u.p2.pP[rr * 37 + 0 * 9 + hp] + u.p2.pP[rr * 37 + 1 * 9 + hp] +
                   u.p2.pP[rr * 37 + 2 * 9 + hp] + u.p2.pP[rr * 37 + 3 * 9 + hp];
        float a1 = u.p2.pP[rr * 37 + 0 * 9 + hp + 4] + u.p2.pP[rr * 37 + 1 * 9 + hp + 4] +
                   u.p2.pP[rr * 37 + 2 * 9 + hp + 4] + u.p2.pP[rr * 37 + 3 * 9 + hp + 4];
        u.p2.sB[hp * 68 + rr] = rstd * a0 - mr * SgW[hp] + SbW[hp];
        u.p2.sB[(hp + 4) * 68 + rr] = rstd * a1 - mr * SgW[hp + 4] + SbW[hp + 4];
    }
    __syncthreads();

    // phase 4: coalesced write 8 heads x 64 j
    if (t < 128) {
        int h = t >> 4, col = (t & 15) * 4;
        float4 v = *(const float4*)&u.p2.sB[h * 68 + col];
        *(float4*)&d_Bt[((size_t)i * NH + h) * L + jbase + col] = v;
    }
}

// ---------------- Kernel 4a: split attention, BM=64 rows, 256 threads ----------------
__global__ __launch_bounds__(256) void attn_split_kernel(const int* __restrict__ mask) {
    __shared__ float Qs[BM][33];
    __shared__ float Ks[BN][33];
    __shared__ float Vs[BN][32];
    __shared__ float Ss[BM][67];
    __shared__ float row_m[BM], row_l[BM], row_alpha[BM];
    __shared__ unsigned char ms[BN];

    int t = threadIdx.x;
    int h = blockIdx.y;
    int i0 = blockIdx.x * BM;
    int split = blockIdx.z;
    int tx = t & 15, ty = t >> 4;

    // load Q pre-scaled (64 x 32)
#pragma unroll
    for (int rep = 0; rep < 2; rep++) {
        int idx = t + rep * 256;
        int r = idx >> 3, dgq = idx & 7;
        float4 q4 = *(const float4*)&d_Q[(i0 + r) * CS + h * DH + dgq * 4];
        Qs[r][dgq * 4 + 0] = q4.x * QK_SCALE;
        Qs[r][dgq * 4 + 1] = q4.y * QK_SCALE;
        Qs[r][dgq * 4 + 2] = q4.z * QK_SCALE;
        Qs[r][dgq * 4 + 3] = q4.w * QK_SCALE;
    }
    if (t < BM) { row_m[t] = -CUDART_INF_F; row_l[t] = 0.f; }

    // PV ownership: 2 rows x 4 d per thread
    int dg = t & 7;
    int r0 = (t >> 3) * 2;
    float4 O0 = make_float4(0.f, 0.f, 0.f, 0.f);
    float4 O1 = make_float4(0.f, 0.f, 0.f, 0.f);

    for (int jt = 0; jt < 4; jt++) {
        int j0 = split * 256 + jt * BN;
        __syncthreads();
        // load K/V tiles
#pragma unroll
        for (int rep = 0; rep < 2; rep++) {
            int idx = t + rep * 256;
            int r = idx >> 3, g = idx & 7;
            float4 k4 = *(const float4*)&d_K[(j0 + r) * CS + h * DH + g * 4];
            Ks[r][g * 4 + 0] = k4.x;
            Ks[r][g * 4 + 1] = k4.y;
            Ks[r][g * 4 + 2] = k4.z;
            Ks[r][g * 4 + 3] = k4.w;
            *(float4*)&Vs[r][g * 4] = *(const float4*)&d_V[(j0 + r) * CS + h * DH + g * 4];
        }
        if (t < BN) ms[t] = (unsigned char)(mask[j0 + t] != 0);
        __syncthreads();

        // S = Q K^T (64x64, 4x4 per thread)
        float sacc[4][4] = {};
#pragma unroll 8
        for (int d = 0; d < 32; d++) {
            float a[4], bb[4];
#pragma unroll
            for (int ii = 0; ii < 4; ii++) a[ii] = Qs[ty * 4 + ii][d];
#pragma unroll
            for (int jj = 0; jj < 4; jj++) bb[jj] = Ks[tx * 4 + jj][d];
#pragma unroll
            for (int ii = 0; ii < 4; ii++)
#pragma unroll
                for (int jj = 0; jj < 4; jj++) sacc[ii][jj] = fmaf(a[ii], bb[jj], sacc[ii][jj]);
        }
        // bias + mask + store S
#pragma unroll
        for (int ii = 0; ii < 4; ii++) {
            int iI = ty * 4 + ii;
            const float4 bv = *(const float4*)&d_Bt[(size_t)(i0 + iI) * (NH * L) + h * L + j0 + tx * 4];
            float bb4[4] = {bv.x, bv.y, bv.z, bv.w};
#pragma unroll
            for (int jj = 0; jj < 4; jj++) {
                int jl = tx * 4 + jj;
                Ss[iI][jl] = ms[jl] ? (sacc[ii][jj] + bb4[jj]) : -CUDART_INF_F;
            }
        }
        __syncthreads();

        // online softmax: rw = t>>2 (64 rows), gq = t&3 (16 j each)
        {
            int rw = t >> 2, gq = t & 3;
            float mold = row_m[rw];
            float mx = -CUDART_INF_F;
#pragma unroll
            for (int qq = 0; qq < 16; qq++) mx = fmaxf(mx, Ss[rw][gq * 16 + qq]);
            mx = fmaxf(mx, __shfl_xor_sync(0xffffffffu, mx, 1));
            mx = fmaxf(mx, __shfl_xor_sync(0xffffffffu, mx, 2));
            float nm = fmaxf(mold, mx);
            float alpha = (nm == -CUDART_INF_F) ? 1.f : __expf(mold - nm);
            float ps = 0.f;
#pragma unroll
            for (int qq = 0; qq < 16; qq++) {
                float sv = Ss[rw][gq * 16 + qq];
                float p = (sv == -CUDART_INF_F) ? 0.f : __expf(sv - nm);
                Ss[rw][gq * 16 + qq] = p;
                ps += p;
            }
            ps += __shfl_xor_sync(0xffffffffu, ps, 1);
            ps += __shfl_xor_sync(0xffffffffu, ps, 2);
            if (gq == 0) {
                row_m[rw] = nm;
                row_l[rw] = row_l[rw] * alpha + ps;
                row_alpha[rw] = alpha;
            }
        }
        __syncthreads();

        // PV: O += P @ V, 2 rows x 4 d per thread
        {
            float a0 = row_alpha[r0], a1 = row_alpha[r0 + 1];
            O0.x *= a0; O0.y *= a0; O0.z *= a0; O0.w *= a0;
            O1.x *= a1; O1.y *= a1; O1.z *= a1; O1.w *= a1;
#pragma unroll 4
            for (int j = 0; j < BN; j++) {
                float p0 = Ss[r0][j];
                float p1 = Ss[r0 + 1][j];
                const float4 v = *(const float4*)&Vs[j][dg * 4];
                O0.x = fmaf(p0, v.x, O0.x);
                O0.y = fmaf(p0, v.y, O0.y);
                O0.z = fmaf(p0, v.z, O0.z);
                O0.w = fmaf(p0, v.w, O0.w);
                O1.x = fmaf(p1, v.x, O1.x);
                O1.y = fmaf(p1, v.y, O1.y);
                O1.z = fmaf(p1, v.z, O1.z);
                O1.w = fmaf(p1, v.w, O1.w);
            }
        }
    }

    // write partials (unnormalized O and per-row m,l)
    {
        size_t b0 = (((size_t)(split * NH + h)) * L + i0 + r0) * DH + dg * 4;
        *(float4*)&d_pO[b0] = O0;
        *(float4*)&d_pO[b0 + DH] = O1;
        if (t < BM) d_pml[((split * NH + h) * L) + i0 + t] = make_float2(row_m[t], row_l[t]);
    }
}

// ---------------- Kernel 4b: combine splits, apply 1/l and G gate ----------------
__global__ __launch_bounds__(256) void attn_combine_kernel() {
    int t = threadIdx.x;
    int i = blockIdx.x;
    int h = t >> 5, lane = t & 31;

    float2 ml[NSPLIT];
    float mx = -CUDART_INF_F;
#pragma unroll
    for (int s = 0; s < NSPLIT; s++) {
        ml[s] = d_pml[((s * NH + h) * L) + i];
        mx = fmaxf(mx, ml[s].x);
    }
    float lsum = 0.f, o = 0.f;
#pragma unroll
    for (int s = 0; s < NSPLIT; s++) {
        float w = (ml[s].x == -CUDART_INF_F) ? 0.f : __expf(ml[s].x - mx);
        lsum = fmaf(ml[s].y, w, lsum);
        o = fmaf(d_pO[(((s * NH + h) * L) + i) * DH + lane], w, o);
    }
    float rl = (lsum > 0.f) ? (1.f / lsum) : 0.f;
    int base = i * CS + h * DH + lane;
    d_AO[base] = o * rl * d_G[base];
}

// ---------------- Kernel 5: ds = (G*out) @ Wo * mask ----------------
__global__ __launch_bounds__(256) void gemm_out_kernel(const float* __restrict__ Wo,
                                                       const int* __restrict__ mask,
                                                       float* __restrict__ out) {
    int m0 = blockIdx.x * 64, n0 = blockIdx.y * 64;
    float acc[4][4] = {};
    gemm_tile_64x64(d_AO, Wo, m0, n0, acc);

    int tx = threadIdx.x & 15, ty = threadIdx.x >> 4;
#pragma unroll
    for (int ii = 0; ii < 4; ii++) {
        int mI = m0 + ty * 4 + ii;
        float mk = (mask[mI] != 0) ? 1.f : 0.f;
#pragma unroll
        for (int jj = 0; jj < 4; jj++) {
            int nI = n0 + tx * 4 + jj;
            out[mI * 256 + nI] = acc[ii][jj] * mk;
        }
    }
}

// ---------------- launch ----------------
extern "C" void kernel_launch(void* const* d_in, const int* in_sizes, int n_in,
                              void* d_out, int out_size) {
    const float* s = (const float*)d_in[0];
    const float* z = (const float*)d_in[1];
    const int* res_mask = (const int*)d_in[2];
    const float* g_s = (const float*)d_in[3];
    const float* b_s = (const float*)d_in[4];
    const float* g_z = (const float*)d_in[5];
    const float* b_z = (const float*)d_in[6];
    const float* Wq = (const float*)d_in[7];
    const float* bq = (const float*)d_in[8];
    const float* Wk = (const float*)d_in[9];
    const float* Wv = (const float*)d_in[10];
    const float* Wb = (const float*)d_in[11];
    const float* Wg = (const float*)d_in[12];
    const float* Wo = (const float*)d_in[13];
    float* out = (float*)d_out;

    ln_s_kernel<<<L, 256>>>(s, g_s, b_s);
    gemm_qkvg_kernel<<<dim3(16, 4, 4), 256>>>(Wq, bq, Wk, Wv, Wg);
    zln_bias_kernel<<<dim3(16, L), 256>>>(z, g_z, b_z, Wb);
    attn_split_kernel<<<dim3(16, 8, NSPLIT), 256>>>(res_mask);
    attn_combine_kernel<<<L, 256>>>();
    gemm_out_kernel<<<dim3(16, 4), 256>>>(Wo, res_mask, out);
}

// round 7
// speedup vs baseline: 1.6387x; 1.2371x over previous
#include <cuda_runtime.h>
#include <math_constants.h>

#define L 1024
#define CS 256
#define CZ 128
#define NH 8
#define DH 32
#define NSPLIT 4
#define BM 64
#define BN 64
#define LN_EPS 1e-5f
#define QK_SCALE 0.17677669529663687f  // 1/sqrt(32)

// f32x2 packed math (sm_103a)
#define PACKF2(d, lo, hi) \
    asm("mov.b64 %0, {%1, %2};" : "=l"(d) : "r"(__float_as_uint(lo)), "r"(__float_as_uint(hi)))
#define UNPACKF2(lo, hi, v) \
    do { unsigned _ulo, _uhi; \
         asm("mov.b64 {%0, %1}, %2;" : "=r"(_ulo), "=r"(_uhi) : "l"(v)); \
         lo = __uint_as_float(_ulo); hi = __uint_as_float(_uhi); } while (0)
#define FMA_F32X2(d, a, b, c) \
    asm("fma.rn.f32x2 %0, %1, %2, %3;" : "=l"(d) : "l"(a), "l"(b), "l"(c))
#define ADD_F32X2(d, a, b) \
    asm("add.rn.f32x2 %0, %1, %2;" : "=l"(d) : "l"(a), "l"(b))

// ---------------- scratch (device globals; no allocation allowed) ----------------
__device__ float d_sln[L * CS];
__device__ float d_Q[L * CS];
__device__ float d_K[L * CS];
__device__ float d_V[L * CS];
__device__ float d_G[L * CS];
__device__ float d_Bt[(size_t)L * NH * L];             // bias transposed: [i][h][j], 32 MB
__device__ float d_AO[L * CS];                         // G * attn_out
__device__ float d_pO[NSPLIT * NH * L * DH];           // split attention partial O
__device__ float2 d_pml[NSPLIT * NH * L];              // split attention partial (m, l)
__device__ float4 d_GW4g[256];                         // packed g*Wb, [q][h*8+k]
__device__ float d_SgWg[NH], d_SbWg[NH];

// ---------------- Kernel 0: one-block prep of GW / SgW / SbW ----------------
__global__ __launch_bounds__(256) void zprep_kernel(const float* __restrict__ gz,
                                                    const float* __restrict__ bz,
                                                    const float* __restrict__ Wb) {
    int t = threadIdx.x;
    {
        int q = t >> 6, rem = t & 63, h = rem >> 3, k = rem & 7;
        int c = q * 32 + k * 4;
        d_GW4g[q * 64 + h * 8 + k] =
            make_float4(gz[c] * Wb[c * NH + h], gz[c + 1] * Wb[(c + 1) * NH + h],
                        gz[c + 2] * Wb[(c + 2) * NH + h], gz[c + 3] * Wb[(c + 3) * NH + h]);
    }
    if (t < 16) {
        int h = t & 7;
        float acc = 0.f;
        if (t < 8) {
            for (int c = 0; c < CZ; c++) acc = fmaf(gz[c], Wb[c * NH + h], acc);
            d_SgWg[h] = acc;
        } else {
            for (int c = 0; c < CZ; c++) acc = fmaf(bz[c], Wb[c * NH + h], acc);
            d_SbWg[h] = acc;
        }
    }
}

// ---------------- Kernel 1: LayerNorm(s) ----------------
__global__ __launch_bounds__(256) void ln_s_kernel(const float* __restrict__ s,
                                                   const float* __restrict__ g,
                                                   const float* __restrict__ b) {
    int r = blockIdx.x, t = threadIdx.x;
    float v = s[r * CS + t];
    __shared__ float red[8];

    float sum = v;
#pragma unroll
    for (int off = 16; off > 0; off >>= 1) sum += __shfl_xor_sync(0xffffffffu, sum, off);
    if ((t & 31) == 0) red[t >> 5] = sum;
    __syncthreads();
    float tot = 0.f;
#pragma unroll
    for (int k = 0; k < 8; k++) tot += red[k];
    float mean = tot * (1.f / CS);
    float d = v - mean;
    __syncthreads();

    float sq = d * d;
#pragma unroll
    for (int off = 16; off > 0; off >>= 1) sq += __shfl_xor_sync(0xffffffffu, sq, off);
    if ((t & 31) == 0) red[t >> 5] = sq;
    __syncthreads();
    float tot2 = 0.f;
#pragma unroll
    for (int k = 0; k < 8; k++) tot2 += red[k];
    float rstd = rsqrtf(tot2 * (1.f / CS) + LN_EPS);

    d_sln[r * CS + t] = d * rstd * g[t] + b[t];
}

// ---------------- shared GEMM tile helper ----------------
__device__ __forceinline__ void gemm_tile_64x64(const float* __restrict__ A,
                                                const float* __restrict__ Bm,
                                                int m0, int n0, float acc[4][4]) {
    __shared__ float As[64][33];
    __shared__ float Bs[32][65];
    int t = threadIdx.x;
    int tx = t & 15, ty = t >> 4;

    for (int k0 = 0; k0 < 256; k0 += 32) {
        int ra = t >> 2, ca = (t & 3) * 8;
#pragma unroll
        for (int q = 0; q < 8; q++) As[ra][ca + q] = A[(m0 + ra) * 256 + k0 + ca + q];
        int rb = t >> 3, cb = (t & 7) * 8;
#pragma unroll
        for (int q = 0; q < 8; q++) Bs[rb][cb + q] = Bm[(k0 + rb) * 256 + n0 + cb + q];
        __syncthreads();
#pragma unroll 8
        for (int kk = 0; kk < 32; kk++) {
            float a[4], bb[4];
#pragma unroll
            for (int ii = 0; ii < 4; ii++) a[ii] = As[ty * 4 + ii][kk];
#pragma unroll
            for (int jj = 0; jj < 4; jj++) bb[jj] = Bs[kk][tx * 4 + jj];
#pragma unroll
            for (int ii = 0; ii < 4; ii++)
#pragma unroll
                for (int jj = 0; jj < 4; jj++) acc[ii][jj] = fmaf(a[ii], bb[jj], acc[ii][jj]);
        }
        __syncthreads();
    }
}

// ---------------- Kernel 2: QKVG projections ----------------
__global__ __launch_bounds__(256) void gemm_qkvg_kernel(const float* __restrict__ Wq,
                                                        const float* __restrict__ bq,
                                                        const float* __restrict__ Wk,
                                                        const float* __restrict__ Wv,
                                                        const float* __restrict__ Wg) {
    const float* Bm;
    float* C;
    int mode;
    switch (blockIdx.z) {
        case 0: Bm = Wq; C = d_Q; mode = 1; break;
        case 1: Bm = Wk; C = d_K; mode = 0; break;
        case 2: Bm = Wv; C = d_V; mode = 0; break;
        default: Bm = Wg; C = d_G; mode = 2; break;
    }
    int m0 = blockIdx.x * 64, n0 = blockIdx.y * 64;
    float acc[4][4] = {};
    gemm_tile_64x64(d_sln, Bm, m0, n0, acc);

    int tx = threadIdx.x & 15, ty = threadIdx.x >> 4;
#pragma unroll
    for (int ii = 0; ii < 4; ii++)
#pragma unroll
        for (int jj = 0; jj < 4; jj++) {
            int mI = m0 + ty * 4 + ii, nI = n0 + tx * 4 + jj;
            float v = acc[ii][jj];
            if (mode == 1) v += bq[nI];
            if (mode == 2) v = 1.f / (1.f + __expf(-v));
            C[mI * 256 + nI] = v;
        }
}

// ---------------- Kernel 3: zln_bias v5 — f32x2 packed FMA + prepped weights ----------------
struct ZPhase2 {
    float pP[64 * 37];
    float2 psum[64][4];
    float sB[NH * 68];
};
union ZUnion {
    float4 zs4[2048];   // 32 KB staging
    ZPhase2 p2;
};

__global__ __launch_bounds__(256) void zln_bias_kernel(const float* __restrict__ z) {
    __shared__ ZUnion u;
    __shared__ ulonglong2 GW2[4][65];    // packed (f32x2 pairs) per [q][h*8+k]
    __shared__ float SgW[NH], SbW[NH];

    int t = threadIdx.x;
    int i = blockIdx.y;
    int jbase = blockIdx.x * 64;

    // phase 0: load prepped weights (coalesced) + swizzled z staging
    {
        float4 w = d_GW4g[t];
        ulonglong2 p;
        PACKF2(p.x, w.x, w.y);
        PACKF2(p.y, w.z, w.w);
        GW2[t >> 6][t & 63] = p;
    }
    if (t < 8) { SgW[t] = d_SgWg[t]; SbW[t] = d_SbWg[t]; }
    {
        const float4* zg = (const float4*)(z + ((size_t)i * L + jbase) * CZ);
#pragma unroll
        for (int p = 0; p < 8; p++) {
            int f = t + p * 256;
            int r = f >> 5, c4 = f & 31;
            int slot = c4 * 64 + (r & 56) + ((r + 2 * (c4 >> 3) + (c4 & 7)) & 7);
            u.zs4[slot] = zg[f];
        }
    }
    __syncthreads();

    // phase 1: consume zs into registers
    int r = t >> 2, q = t & 3;
    float4 zv[8];
#pragma unroll
    for (int k = 0; k < 8; k++) {
        int c4 = q * 8 + k;
        int slot = c4 * 64 + (r & 56) + ((r + 2 * q + k) & 7);
        zv[k] = u.zs4[slot];
    }
    __syncthreads();   // zs consumed; p2 aliasing safe

    // phase 2: packed partial dots (f32x2)
    {
        unsigned long long pa2[8] = {0ull, 0ull, 0ull, 0ull, 0ull, 0ull, 0ull, 0ull};
        unsigned long long s1p = 0ull, s2p = 0ull;
#pragma unroll
        for (int k = 0; k < 8; k++) {
            unsigned long long v01, v23;
            PACKF2(v01, zv[k].x, zv[k].y);
            PACKF2(v23, zv[k].z, zv[k].w);
#pragma unroll
            for (int h = 0; h < 8; h++) {
                ulonglong2 w = GW2[q][h * 8 + k];
                FMA_F32X2(pa2[h], v01, w.x, pa2[h]);
                FMA_F32X2(pa2[h], v23, w.y, pa2[h]);
            }
            FMA_F32X2(s2p, v01, v01, s2p);
            FMA_F32X2(s2p, v23, v23, s2p);
            ADD_F32X2(s1p, s1p, v01);
            ADD_F32X2(s1p, s1p, v23);
        }
#pragma unroll
        for (int h = 0; h < 8; h++) {
            float lo, hi;
            UNPACKF2(lo, hi, pa2[h]);
            u.p2.pP[r * 37 + q * 9 + h] = lo + hi;
        }
        float l1, h1, l2, h2;
        UNPACKF2(l1, h1, s1p);
        UNPACKF2(l2, h2, s2p);
        u.p2.psum[r][q] = make_float2(l1 + h1, l2 + h2);
    }
    __syncthreads();

    // phase 3: combine per row, finish two heads per thread
    {
        int rr = t >> 2, hp = t & 3;
        float2 p0 = u.p2.psum[rr][0], p1 = u.p2.psum[rr][1];
        float2 p2v = u.p2.psum[rr][2], p3 = u.p2.psum[rr][3];
        float s1 = p0.x + p1.x + p2v.x + p3.x;
        float s2 = p0.y + p1.y + p2v.y + p3.y;
        float mean = s1 * (1.f / CZ);
        float rstd = rsqrtf(s2 * (1.f / CZ) - mean * mean + LN_EPS);
        float mr = mean * rstd;

        float a0 = u.p2.pP[rr * 37 + 0 * 9 + hp] + u.p2.pP[rr * 37 + 1 * 9 + hp] +
                   u.p2.pP[rr * 37 + 2 * 9 + hp] + u.p2.pP[rr * 37 + 3 * 9 + hp];
        float a1 = u.p2.pP[rr * 37 + 0 * 9 + hp + 4] + u.p2.pP[rr * 37 + 1 * 9 + hp + 4] +
                   u.p2.pP[rr * 37 + 2 * 9 + hp + 4] + u.p2.pP[rr * 37 + 3 * 9 + hp + 4];
        u.p2.sB[hp * 68 + rr] = rstd * a0 - mr * SgW[hp] + SbW[hp];
        u.p2.sB[(hp + 4) * 68 + rr] = rstd * a1 - mr * SgW[hp + 4] + SbW[hp + 4];
    }
    __syncthreads();

    // phase 4: coalesced write 8 heads x 64 j
    if (t < 128) {
        int h = t >> 4, col = (t & 15) * 4;
        float4 v = *(const float4*)&u.p2.sB[h * 68 + col];
        *(float4*)&d_Bt[((size_t)i * NH + h) * L + jbase + col] = v;
    }
}

// ---------------- Kernel 4a: split attention, BM=64 rows, 256 threads ----------------
__global__ __launch_bounds__(256) void attn_split_kernel(const int* __restrict__ mask) {
    __shared__ float Qs[BM][33];
    __shared__ float Ks[BN][33];
    __shared__ float Vs[BN][32];
    __shared__ float Ss[BM][67];
    __shared__ float row_m[BM], row_l[BM], row_alpha[BM];
    __shared__ unsigned char ms[BN];

    int t = threadIdx.x;
    int h = blockIdx.y;
    int i0 = blockIdx.x * BM;
    int split = blockIdx.z;
    int tx = t & 15, ty = t >> 4;

#pragma unroll
    for (int rep = 0; rep < 2; rep++) {
        int idx = t + rep * 256;
        int r = idx >> 3, dgq = idx & 7;
        float4 q4 = *(const float4*)&d_Q[(i0 + r) * CS + h * DH + dgq * 4];
        Qs[r][dgq * 4 + 0] = q4.x * QK_SCALE;
        Qs[r][dgq * 4 + 1] = q4.y * QK_SCALE;
        Qs[r][dgq * 4 + 2] = q4.z * QK_SCALE;
        Qs[r][dgq * 4 + 3] = q4.w * QK_SCALE;
    }
    if (t < BM) { row_m[t] = -CUDART_INF_F; row_l[t] = 0.f; }

    int dg = t & 7;
    int r0 = (t >> 3) * 2;
    float4 O0 = make_float4(0.f, 0.f, 0.f, 0.f);
    float4 O1 = make_float4(0.f, 0.f, 0.f, 0.f);

    for (int jt = 0; jt < 4; jt++) {
        int j0 = split * 256 + jt * BN;
        __syncthreads();
#pragma unroll
        for (int rep = 0; rep < 2; rep++) {
            int idx = t + rep * 256;
            int r = idx >> 3, g = idx & 7;
            float4 k4 = *(const float4*)&d_K[(j0 + r) * CS + h * DH + g * 4];
            Ks[r][g * 4 + 0] = k4.x;
            Ks[r][g * 4 + 1] = k4.y;
            Ks[r][g * 4 + 2] = k4.z;
            Ks[r][g * 4 + 3] = k4.w;
            *(float4*)&Vs[r][g * 4] = *(const float4*)&d_V[(j0 + r) * CS + h * DH + g * 4];
        }
        if (t < BN) ms[t] = (unsigned char)(mask[j0 + t] != 0);
        __syncthreads();

        float sacc[4][4] = {};
#pragma unroll 8
        for (int d = 0; d < 32; d++) {
            float a[4], bb[4];
#pragma unroll
            for (int ii = 0; ii < 4; ii++) a[ii] = Qs[ty * 4 + ii][d];
#pragma unroll
            for (int jj = 0; jj < 4; jj++) bb[jj] = Ks[tx * 4 + jj][d];
#pragma unroll
            for (int ii = 0; ii < 4; ii++)
#pragma unroll
                for (int jj = 0; jj < 4; jj++) sacc[ii][jj] = fmaf(a[ii], bb[jj], sacc[ii][jj]);
        }
#pragma unroll
        for (int ii = 0; ii < 4; ii++) {
            int iI = ty * 4 + ii;
            const float4 bv = *(const float4*)&d_Bt[(size_t)(i0 + iI) * (NH * L) + h * L + j0 + tx * 4];
            float bb4[4] = {bv.x, bv.y, bv.z, bv.w};
#pragma unroll
            for (int jj = 0; jj < 4; jj++) {
                int jl = tx * 4 + jj;
                Ss[iI][jl] = ms[jl] ? (sacc[ii][jj] + bb4[jj]) : -CUDART_INF_F;
            }
        }
        __syncthreads();

        {
            int rw = t >> 2, gq = t & 3;
            float mold = row_m[rw];
            float mx = -CUDART_INF_F;
#pragma unroll
            for (int qq = 0; qq < 16; qq++) mx = fmaxf(mx, Ss[rw][gq * 16 + qq]);
            mx = fmaxf(mx, __shfl_xor_sync(0xffffffffu, mx, 1));
            mx = fmaxf(mx, __shfl_xor_sync(0xffffffffu, mx, 2));
            float nm = fmaxf(mold, mx);
            float alpha = (nm == -CUDART_INF_F) ? 1.f : __expf(mold - nm);
            float ps = 0.f;
#pragma unroll
            for (int qq = 0; qq < 16; qq++) {
                float sv = Ss[rw][gq * 16 + qq];
                float p = (sv == -CUDART_INF_F) ? 0.f : __expf(sv - nm);
                Ss[rw][gq * 16 + qq] = p;
                ps += p;
            }
            ps += __shfl_xor_sync(0xffffffffu, ps, 1);
            ps += __shfl_xor_sync(0xffffffffu, ps, 2);
            if (gq == 0) {
                row_m[rw] = nm;
                row_l[rw] = row_l[rw] * alpha + ps;
                row_alpha[rw] = alpha;
            }
        }
        __syncthreads();

        {
            float a0 = row_alpha[r0], a1 = row_alpha[r0 + 1];
            O0.x *= a0; O0.y *= a0; O0.z *= a0; O0.w *= a0;
            O1.x *= a1; O1.y *= a1; O1.z *= a1; O1.w *= a1;
#pragma unroll 4
            for (int j = 0; j < BN; j++) {
                float p0 = Ss[r0][j];
                float p1 = Ss[r0 + 1][j];
                const float4 v = *(const float4*)&Vs[j][dg * 4];
                O0.x = fmaf(p0, v.x, O0.x);
                O0.y = fmaf(p0, v.y, O0.y);
                O0.z = fmaf(p0, v.z, O0.z);
                O0.w = fmaf(p0, v.w, O0.w);
                O1.x = fmaf(p1, v.x, O1.x);
                O1.y = fmaf(p1, v.y, O1.y);
                O1.z = fmaf(p1, v.z, O1.z);
                O1.w = fmaf(p1, v.w, O1.w);
            }
        }
    }

    {
        size_t b0 = (((size_t)(split * NH + h)) * L + i0 + r0) * DH + dg * 4;
        *(float4*)&d_pO[b0] = O0;
        *(float4*)&d_pO[b0 + DH] = O1;
        if (t < BM) d_pml[((split * NH + h) * L) + i0 + t] = make_float2(row_m[t], row_l[t]);
    }
}

// ---------------- Kernel 4b: combine splits, apply 1/l and G gate ----------------
__global__ __launch_bounds__(256) void attn_combine_kernel() {
    int t = threadIdx.x;
    int i = blockIdx.x;
    int h = t >> 5, lane = t & 31;

    float2 ml[NSPLIT];
    float mx = -CUDART_INF_F;
#pragma unroll
    for (int s = 0; s < NSPLIT; s++) {
        ml[s] = d_pml[((s * NH + h) * L) + i];
        mx = fmaxf(mx, ml[s].x);
    }
    float lsum = 0.f, o = 0.f;
#pragma unroll
    for (int s = 0; s < NSPLIT; s++) {
        float w = (ml[s].x == -CUDART_INF_F) ? 0.f : __expf(ml[s].x - mx);
        lsum = fmaf(ml[s].y, w, lsum);
        o = fmaf(d_pO[(((s * NH + h) * L) + i) * DH + lane], w, o);
    }
    float rl = (lsum > 0.f) ? (1.f / lsum) : 0.f;
    int base = i * CS + h * DH + lane;
    d_AO[base] = o * rl * d_G[base];
}

// ---------------- Kernel 5: ds = (G*out) @ Wo * mask ----------------
__global__ __launch_bounds__(256) void gemm_out_kernel(const float* __restrict__ Wo,
                                                       const int* __restrict__ mask,
                                                       float* __restrict__ out) {
    int m0 = blockIdx.x * 64, n0 = blockIdx.y * 64;
    float acc[4][4] = {};
    gemm_tile_64x64(d_AO, Wo, m0, n0, acc);

    int tx = threadIdx.x & 15, ty = threadIdx.x >> 4;
#pragma unroll
    for (int ii = 0; ii < 4; ii++) {
        int mI = m0 + ty * 4 + ii;
        float mk = (mask[mI] != 0) ? 1.f : 0.f;
#pragma unroll
        for (int jj = 0; jj < 4; jj++) {
            int nI = n0 + tx * 4 + jj;
            out[mI * 256 + nI] = acc[ii][jj] * mk;
        }
    }
}

// ---------------- launch ----------------
extern "C" void kernel_launch(void* const* d_in, const int* in_sizes, int n_in,
                              void* d_out, int out_size) {
    const float* s = (const float*)d_in[0];
    const float* z = (const float*)d_in[1];
    const int* res_mask = (const int*)d_in[2];
    const float* g_s = (const float*)d_in[3];
    const float* b_s = (const float*)d_in[4];
    const float* g_z = (const float*)d_in[5];
    const float* b_z = (const float*)d_in[6];
    const float* Wq = (const float*)d_in[7];
    const float* bq = (const float*)d_in[8];
    const float* Wk = (const float*)d_in[9];
    const float* Wv = (const float*)d_in[10];
    const float* Wb = (const float*)d_in[11];
    const float* Wg = (const float*)d_in[12];
    const float* Wo = (const float*)d_in[13];
    float* out = (float*)d_out;

    zprep_kernel<<<1, 256>>>(g_z, b_z, Wb);
    ln_s_kernel<<<L, 256>>>(s, g_s, b_s);
    gemm_qkvg_kernel<<<dim3(16, 4, 4), 256>>>(Wq, bq, Wk, Wv, Wg);
    zln_bias_kernel<<<dim3(16, L), 256>>>(z);
    attn_split_kernel<<<dim3(16, 8, NSPLIT), 256>>>(res_mask);
    attn_combine_kernel<<<L, 256>>>();
    gemm_out_kernel<<<dim3(16, 4), 256>>>(Wo, res_mask, out);
}

// round 8
// speedup vs baseline: 1.8960x; 1.1570x over previous
#include <cuda_runtime.h>
#include <math_constants.h>

#define L 1024
#define CS 256
#define CZ 128
#define NH 8
#define DH 32
#define NSPLIT 4
#define BM 64
#define BN 64
#define LN_EPS 1e-5f
#define QK_SCALE 0.17677669529663687f  // 1/sqrt(32)

// f32x2 packed math (sm_103a)
#define PACKF2(d, lo, hi) \
    asm("mov.b64 %0, {%1, %2};" : "=l"(d) : "r"(__float_as_uint(lo)), "r"(__float_as_uint(hi)))
#define UNPACKF2(lo, hi, v) \
    do { unsigned _ulo, _uhi; \
         asm("mov.b64 {%0, %1}, %2;" : "=r"(_ulo), "=r"(_uhi) : "l"(v)); \
         lo = __uint_as_float(_ulo); hi = __uint_as_float(_uhi); } while (0)
#define FMA_F32X2(d, a, b, c) \
    asm("fma.rn.f32x2 %0, %1, %2, %3;" : "=l"(d) : "l"(a), "l"(b), "l"(c))
#define ADD_F32X2(d, a, b) \
    asm("add.rn.f32x2 %0, %1, %2;" : "=l"(d) : "l"(a), "l"(b))

// ---------------- scratch (device globals; no allocation allowed) ----------------
__device__ float d_sln[L * CS];
__device__ float d_Q[L * CS];
__device__ float d_K[L * CS];
__device__ float d_V[L * CS];
__device__ float d_G[L * CS];
__device__ float d_Bt[(size_t)L * NH * L];             // bias transposed: [i][h][j], 32 MB
__device__ float d_AO[L * CS];                         // G * attn_out
__device__ float d_pO[NSPLIT * NH * L * DH];           // split attention partial O
__device__ float2 d_pml[NSPLIT * NH * L];              // split attention partial (m, l)
__device__ float4 d_GW4g[256];                         // packed g*Wb, idx (q,h,k), c=(q+4k)*4
__device__ float d_SgWg[NH], d_SbWg[NH];

// ---------------- Kernel 0: one-block prep of GW / SgW / SbW ----------------
__global__ __launch_bounds__(256) void zprep_kernel(const float* __restrict__ gz,
                                                    const float* __restrict__ bz,
                                                    const float* __restrict__ Wb) {
    int t = threadIdx.x;
    {
        int q = t >> 6, rem = t & 63, h = rem >> 3, k = rem & 7;
        int c = (q + 4 * k) * 4;     // strided c4 ownership
        d_GW4g[q * 64 + h * 8 + k] =
            make_float4(gz[c] * Wb[c * NH + h], gz[c + 1] * Wb[(c + 1) * NH + h],
                        gz[c + 2] * Wb[(c + 2) * NH + h], gz[c + 3] * Wb[(c + 3) * NH + h]);
    }
    if (t < 16) {
        int h = t & 7;
        float acc = 0.f;
        if (t < 8) {
            for (int c = 0; c < CZ; c++) acc = fmaf(gz[c], Wb[c * NH + h], acc);
            d_SgWg[h] = acc;
        } else {
            for (int c = 0; c < CZ; c++) acc = fmaf(bz[c], Wb[c * NH + h], acc);
            d_SbWg[h] = acc;
        }
    }
}

// ---------------- Kernel 1: LayerNorm(s) ----------------
__global__ __launch_bounds__(256) void ln_s_kernel(const float* __restrict__ s,
                                                   const float* __restrict__ g,
                                                   const float* __restrict__ b) {
    int r = blockIdx.x, t = threadIdx.x;
    float v = s[r * CS + t];
    __shared__ float red[8];

    float sum = v;
#pragma unroll
    for (int off = 16; off > 0; off >>= 1) sum += __shfl_xor_sync(0xffffffffu, sum, off);
    if ((t & 31) == 0) red[t >> 5] = sum;
    __syncthreads();
    float tot = 0.f;
#pragma unroll
    for (int k = 0; k < 8; k++) tot += red[k];
    float mean = tot * (1.f / CS);
    float d = v - mean;
    __syncthreads();

    float sq = d * d;
#pragma unroll
    for (int off = 16; off > 0; off >>= 1) sq += __shfl_xor_sync(0xffffffffu, sq, off);
    if ((t & 31) == 0) red[t >> 5] = sq;
    __syncthreads();
    float tot2 = 0.f;
#pragma unroll
    for (int k = 0; k < 8; k++) tot2 += red[k];
    float rstd = rsqrtf(tot2 * (1.f / CS) + LN_EPS);

    d_sln[r * CS + t] = d * rstd * g[t] + b[t];
}

// ---------------- shared GEMM tile helper ----------------
__device__ __forceinline__ void gemm_tile_64x64(const float* __restrict__ A,
                                                const float* __restrict__ Bm,
                                                int m0, int n0, float acc[4][4]) {
    __shared__ float As[64][33];
    __shared__ float Bs[32][65];
    int t = threadIdx.x;
    int tx = t & 15, ty = t >> 4;

    for (int k0 = 0; k0 < 256; k0 += 32) {
        int ra = t >> 2, ca = (t & 3) * 8;
#pragma unroll
        for (int q = 0; q < 8; q++) As[ra][ca + q] = A[(m0 + ra) * 256 + k0 + ca + q];
        int rb = t >> 3, cb = (t & 7) * 8;
#pragma unroll
        for (int q = 0; q < 8; q++) Bs[rb][cb + q] = Bm[(k0 + rb) * 256 + n0 + cb + q];
        __syncthreads();
#pragma unroll 8
        for (int kk = 0; kk < 32; kk++) {
            float a[4], bb[4];
#pragma unroll
            for (int ii = 0; ii < 4; ii++) a[ii] = As[ty * 4 + ii][kk];
#pragma unroll
            for (int jj = 0; jj < 4; jj++) bb[jj] = Bs[kk][tx * 4 + jj];
#pragma unroll
            for (int ii = 0; ii < 4; ii++)
#pragma unroll
                for (int jj = 0; jj < 4; jj++) acc[ii][jj] = fmaf(a[ii], bb[jj], acc[ii][jj]);
        }
        __syncthreads();
    }
}

// ---------------- Kernel 2: QKVG projections ----------------
__global__ __launch_bounds__(256) void gemm_qkvg_kernel(const float* __restrict__ Wq,
                                                        const float* __restrict__ bq,
                                                        const float* __restrict__ Wk,
                                                        const float* __restrict__ Wv,
                                                        const float* __restrict__ Wg) {
    const float* Bm;
    float* C;
    int mode;
    switch (blockIdx.z) {
        case 0: Bm = Wq; C = d_Q; mode = 1; break;
        case 1: Bm = Wk; C = d_K; mode = 0; break;
        case 2: Bm = Wv; C = d_V; mode = 0; break;
        default: Bm = Wg; C = d_G; mode = 2; break;
    }
    int m0 = blockIdx.x * 64, n0 = blockIdx.y * 64;
    float acc[4][4] = {};
    gemm_tile_64x64(d_sln, Bm, m0, n0, acc);

    int tx = threadIdx.x & 15, ty = threadIdx.x >> 4;
#pragma unroll
    for (int ii = 0; ii < 4; ii++)
#pragma unroll
        for (int jj = 0; jj < 4; jj++) {
            int mI = m0 + ty * 4 + ii, nI = n0 + tx * 4 + jj;
            float v = acc[ii][jj];
            if (mode == 1) v += bq[nI];
            if (mode == 2) v = 1.f / (1.f + __expf(-v));
            C[mI * 256 + nI] = v;
        }
}

// ---------------- Kernel 3: zln_bias v6 — no staging, strided direct LDG, 2 rows/thread ----------------
// Block = (128 j-rows, one i). Thread (rr = t>>2, q = t&3) owns rows rr and rr+64,
// c-chunks c4 = q + 4k (k=0..7): warp LDG touches 64B contiguous per row (nL=8).
__global__ __launch_bounds__(256) void zln_bias_kernel(const float* __restrict__ z) {
    __shared__ ulonglong2 GW2[4][65];    // packed weights, [q][h*8+k]
    __shared__ float SgW[NH], SbW[NH];
    __shared__ float pP[128 * 36];       // partials [r][q*9+h], bank = 4r+9q+h (conflict-free)
    __shared__ float2 psum[128][4];
    __shared__ float sB[NH * 132];

    int t = threadIdx.x;
    int i = blockIdx.y;
    int jbase = blockIdx.x * 128;
    int rr = t >> 2, q = t & 3;

    {
        float4 w = d_GW4g[t];
        ulonglong2 p;
        PACKF2(p.x, w.x, w.y);
        PACKF2(p.y, w.z, w.w);
        GW2[t >> 6][t & 63] = p;
    }
    if (t < 8) { SgW[t] = d_SgWg[t]; SbW[t] = d_SbWg[t]; }
    __syncthreads();

    const float* rowA = z + ((size_t)i * L + jbase + rr) * CZ;
    const float* rowB = rowA + (size_t)64 * CZ;

    unsigned long long paA[8] = {}, paB[8] = {};
    unsigned long long s1A = 0ull, s2A = 0ull, s1B = 0ull, s2B = 0ull;
#pragma unroll
    for (int k = 0; k < 8; k++) {
        int off = (q + 4 * k) * 4;
        const float4 va = *(const float4*)(rowA + off);
        const float4 vb = *(const float4*)(rowB + off);
        unsigned long long a01, a23, b01, b23;
        PACKF2(a01, va.x, va.y);
        PACKF2(a23, va.z, va.w);
        PACKF2(b01, vb.x, vb.y);
        PACKF2(b23, vb.z, vb.w);
#pragma unroll
        for (int h = 0; h < 8; h++) {
            ulonglong2 w = GW2[q][h * 8 + k];
            FMA_F32X2(paA[h], a01, w.x, paA[h]);
            FMA_F32X2(paA[h], a23, w.y, paA[h]);
            FMA_F32X2(paB[h], b01, w.x, paB[h]);
            FMA_F32X2(paB[h], b23, w.y, paB[h]);
        }
        FMA_F32X2(s2A, a01, a01, s2A);
        FMA_F32X2(s2A, a23, a23, s2A);
        ADD_F32X2(s1A, s1A, a01);
        ADD_F32X2(s1A, s1A, a23);
        FMA_F32X2(s2B, b01, b01, s2B);
        FMA_F32X2(s2B, b23, b23, s2B);
        ADD_F32X2(s1B, s1B, b01);
        ADD_F32X2(s1B, s1B, b23);
    }
#pragma unroll
    for (int h = 0; h < 8; h++) {
        float lo, hi;
        UNPACKF2(lo, hi, paA[h]);
        pP[rr * 36 + q * 9 + h] = lo + hi;
        UNPACKF2(lo, hi, paB[h]);
        pP[(rr + 64) * 36 + q * 9 + h] = lo + hi;
    }
    {
        float l1, h1, l2, h2;
        UNPACKF2(l1, h1, s1A);
        UNPACKF2(l2, h2, s2A);
        psum[rr][q] = make_float2(l1 + h1, l2 + h2);
        UNPACKF2(l1, h1, s1B);
        UNPACKF2(l2, h2, s2B);
        psum[rr + 64][q] = make_float2(l1 + h1, l2 + h2);
    }
    __syncthreads();

    // combine: thread (r3 = t>>1, half hb = (t&1)*4), finishes 4 heads of one row
    {
        int r3 = t >> 1, hb = (t & 1) * 4;
        float2 p0 = psum[r3][0], p1 = psum[r3][1], p2v = psum[r3][2], p3 = psum[r3][3];
        float s1 = p0.x + p1.x + p2v.x + p3.x;
        float s2 = p0.y + p1.y + p2v.y + p3.y;
        float mean = s1 * (1.f / CZ);
        float rstd = rsqrtf(s2 * (1.f / CZ) - mean * mean + LN_EPS);
        float mr = mean * rstd;
#pragma unroll
        for (int hh = 0; hh < 4; hh++) {
            int h = hb + hh;
            float a = pP[r3 * 36 + 0 * 9 + h] + pP[r3 * 36 + 1 * 9 + h] +
                      pP[r3 * 36 + 2 * 9 + h] + pP[r3 * 36 + 3 * 9 + h];
            sB[h * 132 + r3] = rstd * a - mr * SgW[h] + SbW[h];
        }
    }
    __syncthreads();

    // coalesced write: 8 heads x 128 j = 256 float4
    {
        int h = t >> 5, col = (t & 31) * 4;
        float4 v = *(const float4*)&sB[h * 132 + col];
        *(float4*)&d_Bt[((size_t)i * NH + h) * L + jbase + col] = v;
    }
}

// ---------------- Kernel 4a: split attention, BM=64 rows, 256 threads ----------------
__global__ __launch_bounds__(256) void attn_split_kernel(const int* __restrict__ mask) {
    __shared__ float Qs[BM][33];
    __shared__ float Ks[BN][33];
    __shared__ float Vs[BN][32];
    __shared__ float Ss[BM][67];
    __shared__ float row_m[BM], row_l[BM], row_alpha[BM];
    __shared__ unsigned char ms[BN];

    int t = threadIdx.x;
    int h = blockIdx.y;
    int i0 = blockIdx.x * BM;
    int split = blockIdx.z;
    int tx = t & 15, ty = t >> 4;

#pragma unroll
    for (int rep = 0; rep < 2; rep++) {
        int idx = t + rep * 256;
        int r = idx >> 3, dgq = idx & 7;
        float4 q4 = *(const float4*)&d_Q[(i0 + r) * CS + h * DH + dgq * 4];
        Qs[r][dgq * 4 + 0] = q4.x * QK_SCALE;
        Qs[r][dgq * 4 + 1] = q4.y * QK_SCALE;
        Qs[r][dgq * 4 + 2] = q4.z * QK_SCALE;
        Qs[r][dgq * 4 + 3] = q4.w * QK_SCALE;
    }
    if (t < BM) { row_m[t] = -CUDART_INF_F; row_l[t] = 0.f; }

    int dg = t & 7;
    int r0 = (t >> 3) * 2;
    float4 O0 = make_float4(0.f, 0.f, 0.f, 0.f);
    float4 O1 = make_float4(0.f, 0.f, 0.f, 0.f);

    for (int jt = 0; jt < 4; jt++) {
        int j0 = split * 256 + jt * BN;
        __syncthreads();
#pragma unroll
        for (int rep = 0; rep < 2; rep++) {
            int idx = t + rep * 256;
            int r = idx >> 3, g = idx & 7;
            float4 k4 = *(const float4*)&d_K[(j0 + r) * CS + h * DH + g * 4];
            Ks[r][g * 4 + 0] = k4.x;
            Ks[r][g * 4 + 1] = k4.y;
            Ks[r][g * 4 + 2] = k4.z;
            Ks[r][g * 4 + 3] = k4.w;
            *(float4*)&Vs[r][g * 4] = *(const float4*)&d_V[(j0 + r) * CS + h * DH + g * 4];
        }
        if (t < BN) ms[t] = (unsigned char)(mask[j0 + t] != 0);
        __syncthreads();

        float sacc[4][4] = {};
#pragma unroll 8
        for (int d = 0; d < 32; d++) {
            float a[4], bb[4];
#pragma unroll
            for (int ii = 0; ii < 4; ii++) a[ii] = Qs[ty * 4 + ii][d];
#pragma unroll
            for (int jj = 0; jj < 4; jj++) bb[jj] = Ks[tx * 4 + jj][d];
#pragma unroll
            for (int ii = 0; ii < 4; ii++)
#pragma unroll
                for (int jj = 0; jj < 4; jj++) sacc[ii][jj] = fmaf(a[ii], bb[jj], sacc[ii][jj]);
        }
#pragma unroll
        for (int ii = 0; ii < 4; ii++) {
            int iI = ty * 4 + ii;
            const float4 bv = *(const float4*)&d_Bt[(size_t)(i0 + iI) * (NH * L) + h * L + j0 + tx * 4];
            float bb4[4] = {bv.x, bv.y, bv.z, bv.w};
#pragma unroll
            for (int jj = 0; jj < 4; jj++) {
                int jl = tx * 4 + jj;
                Ss[iI][jl] = ms[jl] ? (sacc[ii][jj] + bb4[jj]) : -CUDART_INF_F;
            }
        }
        __syncthreads();

        {
            int rw = t >> 2, gq = t & 3;
            float mold = row_m[rw];
            float mx = -CUDART_INF_F;
#pragma unroll
            for (int qq = 0; qq < 16; qq++) mx = fmaxf(mx, Ss[rw][gq * 16 + qq]);
            mx = fmaxf(mx, __shfl_xor_sync(0xffffffffu, mx, 1));
            mx = fmaxf(mx, __shfl_xor_sync(0xffffffffu, mx, 2));
            float nm = fmaxf(mold, mx);
            float alpha = (nm == -CUDART_INF_F) ? 1.f : __expf(mold - nm);
            float ps = 0.f;
#pragma unroll
            for (int qq = 0; qq < 16; qq++) {
                float sv = Ss[rw][gq * 16 + qq];
                float p = (sv == -CUDART_INF_F) ? 0.f : __expf(sv - nm);
                Ss[rw][gq * 16 + qq] = p;
                ps += p;
            }
            ps += __shfl_xor_sync(0xffffffffu, ps, 1);
            ps += __shfl_xor_sync(0xffffffffu, ps, 2);
            if (gq == 0) {
                row_m[rw] = nm;
                row_l[rw] = row_l[rw] * alpha + ps;
                row_alpha[rw] = alpha;
            }
        }
        __syncthreads();

        {
            float a0 = row_alpha[r0], a1 = row_alpha[r0 + 1];
            O0.x *= a0; O0.y *= a0; O0.z *= a0; O0.w *= a0;
            O1.x *= a1; O1.y *= a1; O1.z *= a1; O1.w *= a1;
#pragma unroll 4
            for (int j = 0; j < BN; j++) {
                float p0 = Ss[r0][j];
                float p1 = Ss[r0 + 1][j];
                const float4 v = *(const float4*)&Vs[j][dg * 4];
                O0.x = fmaf(p0, v.x, O0.x);
                O0.y = fmaf(p0, v.y, O0.y);
                O0.z = fmaf(p0, v.z, O0.z);
                O0.w = fmaf(p0, v.w, O0.w);
                O1.x = fmaf(p1, v.x, O1.x);
                O1.y = fmaf(p1, v.y, O1.y);
                O1.z = fmaf(p1, v.z, O1.z);
                O1.w = fmaf(p1, v.w, O1.w);
            }
        }
    }

    {
        size_t b0 = (((size_t)(split * NH + h)) * L + i0 + r0) * DH + dg * 4;
        *(float4*)&d_pO[b0] = O0;
        *(float4*)&d_pO[b0 + DH] = O1;
        if (t < BM) d_pml[((split * NH + h) * L) + i0 + t] = make_float2(row_m[t], row_l[t]);
    }
}

// ---------------- Kernel 4b: combine splits, apply 1/l and G gate ----------------
__global__ __launch_bounds__(256) void attn_combine_kernel() {
    int t = threadIdx.x;
    int i = blockIdx.x;
    int h = t >> 5, lane = t & 31;

    float2 ml[NSPLIT];
    float mx = -CUDART_INF_F;
#pragma unroll
    for (int s = 0; s < NSPLIT; s++) {
        ml[s] = d_pml[((s * NH + h) * L) + i];
        mx = fmaxf(mx, ml[s].x);
    }
    float lsum = 0.f, o = 0.f;
#pragma unroll
    for (int s = 0; s < NSPLIT; s++) {
        float w = (ml[s].x == -CUDART_INF_F) ? 0.f : __expf(ml[s].x - mx);
        lsum = fmaf(ml[s].y, w, lsum);
        o = fmaf(d_pO[(((s * NH + h) * L) + i) * DH + lane], w, o);
    }
    float rl = (lsum > 0.f) ? (1.f / lsum) : 0.f;
    int base = i * CS + h * DH + lane;
    d_AO[base] = o * rl * d_G[base];
}

// ---------------- Kernel 5: ds = (G*out) @ Wo * mask ----------------
__global__ __launch_bounds__(256) void gemm_out_kernel(const float* __restrict__ Wo,
                                                       const int* __restrict__ mask,
                                                       float* __restrict__ out) {
    int m0 = blockIdx.x * 64, n0 = blockIdx.y * 64;
    float acc[4][4] = {};
    gemm_tile_64x64(d_AO, Wo, m0, n0, acc);

    int tx = threadIdx.x & 15, ty = threadIdx.x >> 4;
#pragma unroll
    for (int ii = 0; ii < 4; ii++) {
        int mI = m0 + ty * 4 + ii;
        float mk = (mask[mI] != 0) ? 1.f : 0.f;
#pragma unroll
        for (int jj = 0; jj < 4; jj++) {
            int nI = n0 + tx * 4 + jj;
            out[mI * 256 + nI] = acc[ii][jj] * mk;
        }
    }
}

// ---------------- launch ----------------
extern "C" void kernel_launch(void* const* d_in, const int* in_sizes, int n_in,
                              void* d_out, int out_size) {
    const float* s = (const float*)d_in[0];
    const float* z = (const float*)d_in[1];
    const int* res_mask = (const int*)d_in[2];
    const float* g_s = (const float*)d_in[3];
    const float* b_s = (const float*)d_in[4];
    const float* g_z = (const float*)d_in[5];
    const float* b_z = (const float*)d_in[6];
    const float* Wq = (const float*)d_in[7];
    const float* bq = (const float*)d_in[8];
    const float* Wk = (const float*)d_in[9];
    const float* Wv = (const float*)d_in[10];
    const float* Wb = (const float*)d_in[11];
    const float* Wg = (const float*)d_in[12];
    const float* Wo = (const float*)d_in[13];
    float* out = (float*)d_out;

    zprep_kernel<<<1, 256>>>(g_z, b_z, Wb);
    ln_s_kernel<<<L, 256>>>(s, g_s, b_s);
    gemm_qkvg_kernel<<<dim3(16, 4, 4), 256>>>(Wq, bq, Wk, Wv, Wg);
    zln_bias_kernel<<<dim3(8, L), 256>>>(z);
    attn_split_kernel<<<dim3(16, 8, NSPLIT), 256>>>(res_mask);
    attn_combine_kernel<<<L, 256>>>();
    gemm_out_kernel<<<dim3(16, 4), 256>>>(Wo, res_mask, out);
}